// round 2
// baseline (speedup 1.0000x reference)
#include <cuda_runtime.h>
#include <math.h>

// Problem constants
#define BSQ   4096          // B_s == B_q
#define CDIM  1024          // C
#define NTOT  8192          // B_s + B_q
#define HD    1024          // HEAD_DIM
#define QKN   2048          // q+k columns (v is unused in the reference!)
#define ATTN_SCALE 0.17677669529663687f   // 1024^-0.25 = 2^-2.5

// ---------------------------------------------------------------------------
// Scratch (device globals: no allocation allowed in kernel_launch)
// ---------------------------------------------------------------------------
static __device__ float g_c [(size_t)NTOT * CDIM];   // 32 MB  : [t ; query]
static __device__ float g_qk[(size_t)NTOT * QKN];    // 64 MB  : [q | k], pre-scaled
static __device__ float g_S [(size_t)NTOT * NTOT];   // 256 MB : logits -> probs
static __device__ float g_t0[(size_t)BSQ * HD];      // 16 MB  : attn_cq @ query
static __device__ float g_t1[(size_t)BSQ * HD];      // 16 MB  : attn_qc @ s

// ---------------------------------------------------------------------------
// build c = [s + TG_prompt ; query]   (float4, 1M threads, 2 stores each)
// ---------------------------------------------------------------------------
__global__ __launch_bounds__(256) void build_c(const float* __restrict__ s,
                                               const float* __restrict__ tg,
                                               const float* __restrict__ q)
{
    const size_t i = (size_t)blockIdx.x * blockDim.x + threadIdx.x;      // < 1048576
    const float4* s4  = (const float4*)s;
    const float4* tg4 = (const float4*)tg;
    const float4* q4  = (const float4*)q;
    float4* c4 = (float4*)g_c;
    float4 a = s4[i], b = tg4[i];
    float4 r; r.x = a.x + b.x; r.y = a.y + b.y; r.z = a.z + b.z; r.w = a.w + b.w;
    c4[i] = r;
    c4[i + (size_t)BSQ * CDIM / 4] = q4[i];
}

// ---------------------------------------------------------------------------
// SGEMM NT:  C[m][n] = alpha * sum_k A[m][k] * B[n][k]
// A: M x K row-major (lda), B: N x K row-major (ldb), C: M x N (ldc)
// grid = (N/128, M/128), 256 threads, 8x8 microtile, BK=16
// ---------------------------------------------------------------------------
__global__ __launch_bounds__(256) void gemm_nt(
    const float* __restrict__ A, int lda,
    const float* __restrict__ B, int ldb,
    float* __restrict__ C, int ldc,
    int K, float alpha)
{
    __shared__ float As[16][132];
    __shared__ float Bs[16][132];
    const int tid   = threadIdx.x;
    const int mBase = blockIdx.y * 128;
    const int nBase = blockIdx.x * 128;

    const int lrow = tid >> 2;          // 0..63
    const int lq   = (tid & 3) << 2;    // 0,4,8,12
    const float* Ap = A + (size_t)(mBase + lrow) * lda + lq;
    const float* Bp = B + (size_t)(nBase + lrow) * ldb + lq;

    const int tr = (tid >> 4) << 3;     // 0..120
    const int tc = (tid & 15) << 3;

    float acc[8][8];
#pragma unroll
    for (int i = 0; i < 8; ++i)
#pragma unroll
        for (int j = 0; j < 8; ++j) acc[i][j] = 0.0f;

    for (int k0 = 0; k0 < K; k0 += 16) {
        float4 a0 = *(const float4*)(Ap + k0);
        float4 a1 = *(const float4*)(Ap + k0 + (size_t)64 * lda);
        float4 b0 = *(const float4*)(Bp + k0);
        float4 b1 = *(const float4*)(Bp + k0 + (size_t)64 * ldb);
        __syncthreads();
        As[lq+0][lrow] = a0.x; As[lq+1][lrow] = a0.y; As[lq+2][lrow] = a0.z; As[lq+3][lrow] = a0.w;
        As[lq+0][lrow+64] = a1.x; As[lq+1][lrow+64] = a1.y; As[lq+2][lrow+64] = a1.z; As[lq+3][lrow+64] = a1.w;
        Bs[lq+0][lrow] = b0.x; Bs[lq+1][lrow] = b0.y; Bs[lq+2][lrow] = b0.z; Bs[lq+3][lrow] = b0.w;
        Bs[lq+0][lrow+64] = b1.x; Bs[lq+1][lrow+64] = b1.y; Bs[lq+2][lrow+64] = b1.z; Bs[lq+3][lrow+64] = b1.w;
        __syncthreads();
#pragma unroll
        for (int kk = 0; kk < 16; ++kk) {
            float4 av0 = *(const float4*)&As[kk][tr];
            float4 av1 = *(const float4*)&As[kk][tr + 4];
            float4 bv0 = *(const float4*)&Bs[kk][tc];
            float4 bv1 = *(const float4*)&Bs[kk][tc + 4];
            float a[8] = {av0.x, av0.y, av0.z, av0.w, av1.x, av1.y, av1.z, av1.w};
            float b[8] = {bv0.x, bv0.y, bv0.z, bv0.w, bv1.x, bv1.y, bv1.z, bv1.w};
#pragma unroll
            for (int i = 0; i < 8; ++i)
#pragma unroll
                for (int j = 0; j < 8; ++j) acc[i][j] += a[i] * b[j];
        }
    }

#pragma unroll
    for (int i = 0; i < 8; ++i) {
        float* Cp = C + (size_t)(mBase + tr + i) * ldc + nBase + tc;
        float4 o0, o1;
        o0.x = alpha*acc[i][0]; o0.y = alpha*acc[i][1]; o0.z = alpha*acc[i][2]; o0.w = alpha*acc[i][3];
        o1.x = alpha*acc[i][4]; o1.y = alpha*acc[i][5]; o1.z = alpha*acc[i][6]; o1.w = alpha*acc[i][7];
        *(float4*)Cp       = o0;
        *(float4*)(Cp + 4) = o1;
    }
}

// ---------------------------------------------------------------------------
// SGEMM NN:  C[m][n] = sum_k A[m][k] * B[k][n]
// A: M x K row-major (lda), B: K x N row-major (ldb), C: M x N (ldc)
// ---------------------------------------------------------------------------
__global__ __launch_bounds__(256) void gemm_nn(
    const float* __restrict__ A, int lda,
    const float* __restrict__ B, int ldb,
    float* __restrict__ C, int ldc,
    int K)
{
    __shared__ float As[16][132];
    __shared__ float Bs[16][132];
    const int tid   = threadIdx.x;
    const int mBase = blockIdx.y * 128;
    const int nBase = blockIdx.x * 128;

    const int lrow = tid >> 2;          // A loader: 0..63
    const int lq   = (tid & 3) << 2;
    const float* Ap = A + (size_t)(mBase + lrow) * lda + lq;

    const int bro = tid >> 5;           // B loader: 0..7
    const int bco = (tid & 31) << 2;    // 0..124
    const float* Bp = B + (size_t)bro * ldb + nBase + bco;

    const int tr = (tid >> 4) << 3;
    const int tc = (tid & 15) << 3;

    float acc[8][8];
#pragma unroll
    for (int i = 0; i < 8; ++i)
#pragma unroll
        for (int j = 0; j < 8; ++j) acc[i][j] = 0.0f;

    for (int k0 = 0; k0 < K; k0 += 16) {
        float4 a0 = *(const float4*)(Ap + k0);
        float4 a1 = *(const float4*)(Ap + k0 + (size_t)64 * lda);
        float4 b0 = *(const float4*)(Bp + (size_t)k0 * ldb);
        float4 b1 = *(const float4*)(Bp + (size_t)(k0 + 8) * ldb);
        __syncthreads();
        As[lq+0][lrow] = a0.x; As[lq+1][lrow] = a0.y; As[lq+2][lrow] = a0.z; As[lq+3][lrow] = a0.w;
        As[lq+0][lrow+64] = a1.x; As[lq+1][lrow+64] = a1.y; As[lq+2][lrow+64] = a1.z; As[lq+3][lrow+64] = a1.w;
        *(float4*)&Bs[bro][bco]     = b0;
        *(float4*)&Bs[bro + 8][bco] = b1;
        __syncthreads();
#pragma unroll
        for (int kk = 0; kk < 16; ++kk) {
            float4 av0 = *(const float4*)&As[kk][tr];
            float4 av1 = *(const float4*)&As[kk][tr + 4];
            float4 bv0 = *(const float4*)&Bs[kk][tc];
            float4 bv1 = *(const float4*)&Bs[kk][tc + 4];
            float a[8] = {av0.x, av0.y, av0.z, av0.w, av1.x, av1.y, av1.z, av1.w};
            float b[8] = {bv0.x, bv0.y, bv0.z, bv0.w, bv1.x, bv1.y, bv1.z, bv1.w};
#pragma unroll
            for (int i = 0; i < 8; ++i)
#pragma unroll
                for (int j = 0; j < 8; ++j) acc[i][j] += a[i] * b[j];
        }
    }

#pragma unroll
    for (int i = 0; i < 8; ++i) {
        float* Cp = C + (size_t)(mBase + tr + i) * ldc + nBase + tc;
        float4 o0, o1;
        o0.x = acc[i][0]; o0.y = acc[i][1]; o0.z = acc[i][2]; o0.w = acc[i][3];
        o1.x = acc[i][4]; o1.y = acc[i][5]; o1.z = acc[i][6]; o1.w = acc[i][7];
        *(float4*)Cp       = o0;
        *(float4*)(Cp + 4) = o1;
    }
}

// ---------------------------------------------------------------------------
// Row softmax in place: one CTA (512 threads) per 8192-wide row, regs hold row
// ---------------------------------------------------------------------------
__global__ __launch_bounds__(512) void softmax_row(float* __restrict__ S)
{
    float* p = S + (size_t)blockIdx.x * NTOT;
    const int t = threadIdx.x;
    float v[16];
    float m = -1e30f;
#pragma unroll
    for (int i = 0; i < 16; ++i) { v[i] = p[t + i * 512]; m = fmaxf(m, v[i]); }

    __shared__ float red[16];
#pragma unroll
    for (int o = 16; o; o >>= 1) m = fmaxf(m, __shfl_xor_sync(0xffffffffu, m, o));
    if ((t & 31) == 0) red[t >> 5] = m;
    __syncthreads();
    float mm = red[0];
#pragma unroll
    for (int i = 1; i < 16; ++i) mm = fmaxf(mm, red[i]);

    float sum = 0.0f;
#pragma unroll
    for (int i = 0; i < 16; ++i) { v[i] = __expf(v[i] - mm); sum += v[i]; }
#pragma unroll
    for (int o = 16; o; o >>= 1) sum += __shfl_xor_sync(0xffffffffu, sum, o);
    __syncthreads();
    if ((t & 31) == 0) red[t >> 5] = sum;
    __syncthreads();
    float tot = 0.0f;
#pragma unroll
    for (int i = 0; i < 16; ++i) tot += red[i];
    const float r = 1.0f / tot;
#pragma unroll
    for (int i = 0; i < 16; ++i) p[t + i * 512] = v[i] * r;
}

// ---------------------------------------------------------------------------
extern "C" void kernel_launch(void* const* d_in, const int* in_sizes, int n_in,
                              void* d_out, int out_size)
{
    const float* query = (const float*)d_in[0];
    const float* s     = (const float*)d_in[1];
    const float* tg    = (const float*)d_in[2];
    const float* Wqkv  = (const float*)d_in[3];
    const float* Wps   = (const float*)d_in[4];
    const float* Wpq   = (const float*)d_in[5];
    float* out = (float*)d_out;

    float *c, *qk, *S, *t0, *t1;
    cudaGetSymbolAddress((void**)&c,  g_c);
    cudaGetSymbolAddress((void**)&qk, g_qk);
    cudaGetSymbolAddress((void**)&S,  g_S);
    cudaGetSymbolAddress((void**)&t0, g_t0);
    cudaGetSymbolAddress((void**)&t1, g_t1);

    // 1) c = [s + TG ; query]
    build_c<<<(BSQ * CDIM / 4) / 256, 256>>>(s, tg, query);

    // 2) qk = c @ Wqk^T * SCALE   (only q,k — v is unused)
    gemm_nt<<<dim3(QKN / 128, NTOT / 128), 256>>>(c, CDIM, Wqkv, CDIM,
                                                  qk, QKN, CDIM, ATTN_SCALE);

    // 3) S = q @ k^T  (both pre-scaled)
    gemm_nt<<<dim3(NTOT / 128, NTOT / 128), 256>>>(qk, QKN, qk + HD, QKN,
                                                   S, NTOT, HD, 1.0f);

    // 4) P = softmax(S) rows, in place
    softmax_row<<<NTOT, 512>>>(S);

    // 5) t0 = P[:4096, 4096:] @ query ;  t1 = P[4096:, :4096] @ s
    gemm_nn<<<dim3(HD / 128, BSQ / 128), 256>>>(S + BSQ, NTOT, query, CDIM,
                                                t0, HD, BSQ);
    gemm_nn<<<dim3(HD / 128, BSQ / 128), 256>>>(S + (size_t)BSQ * NTOT, NTOT, s, CDIM,
                                                t1, HD, BSQ);

    // 6) x_s = t0 @ Wps^T ; x_q = t1 @ Wpq^T
    gemm_nt<<<dim3(HD / 128, BSQ / 128), 256>>>(t0, HD, Wps, HD,
                                                out, HD, HD, 1.0f);
    gemm_nt<<<dim3(HD / 128, BSQ / 128), 256>>>(t1, HD, Wpq, HD,
                                                out + (size_t)BSQ * HD, HD, HD, 1.0f);
}

// round 6
// speedup vs baseline: 1.4459x; 1.4459x over previous
#include <cuda_runtime.h>
#include <cuda_bf16.h>
#include <cstdint>
#include <math.h>

// ---------------------------------------------------------------- constants
#define BSQ   4096
#define CDIM  1024
#define NTOT  8192
#define HD    1024
#define QKN   2048
#define SCALE_F 0.17677669529663687f   // 1024^-0.25

// GEMM config: CTA 128x128, k-chunk 32, double-buffered
#define ROWB      80                    // smem row stride bytes (40 bf16)
#define MAT_BYTES (128 * ROWB)          // 10240
#define STG_BYTES (4 * MAT_BYTES)       // Ah,Al,Bh,Bl = 40960
#define SMEM_GEMM (2 * STG_BYTES)       // 81920

// ---------------------------------------------------------------- scratch
static __device__ float          g_S  [(size_t)NTOT*NTOT];     // 256 MB
static __device__ __nv_bfloat16  g_ch [(size_t)NTOT*CDIM],  g_cl [(size_t)NTOT*CDIM];
static __device__ __nv_bfloat16  g_wqkh[(size_t)QKN*CDIM],  g_wqkl[(size_t)QKN*CDIM];
static __device__ __nv_bfloat16  g_wpsh[(size_t)HD*HD],     g_wpsl[(size_t)HD*HD];
static __device__ __nv_bfloat16  g_wpqh[(size_t)HD*HD],     g_wpql[(size_t)HD*HD];
static __device__ __nv_bfloat16  g_qkh[(size_t)NTOT*QKN],   g_qkl[(size_t)NTOT*QKN];
static __device__ __nv_bfloat16  g_pcqh[(size_t)BSQ*BSQ],   g_pcql[(size_t)BSQ*BSQ];
static __device__ __nv_bfloat16  g_pqch[(size_t)BSQ*BSQ],   g_pqcl[(size_t)BSQ*BSQ];
static __device__ __nv_bfloat16  g_qTh[(size_t)CDIM*BSQ],   g_qTl[(size_t)CDIM*BSQ];
static __device__ __nv_bfloat16  g_sTh[(size_t)CDIM*BSQ],   g_sTl[(size_t)CDIM*BSQ];
static __device__ __nv_bfloat16  g_t0h[(size_t)BSQ*HD],     g_t0l[(size_t)BSQ*HD];
static __device__ __nv_bfloat16  g_t1h[(size_t)BSQ*HD],     g_t1l[(size_t)BSQ*HD];

// ---------------------------------------------------------------- helpers
__device__ __forceinline__ uint32_t smem_u32(const void* p) {
    uint32_t a;
    asm("{ .reg .u64 t; cvta.to.shared.u64 t, %1; cvt.u32.u64 %0, t; }" : "=r"(a) : "l"(p));
    return a;
}
__device__ __forceinline__ void cp16(uint32_t dst, const void* src) {
    asm volatile("cp.async.cg.shared.global [%0], [%1], 16;" :: "r"(dst), "l"(src) : "memory");
}
#define CP_COMMIT() asm volatile("cp.async.commit_group;" ::: "memory")
#define CP_WAIT(n)  asm volatile("cp.async.wait_group %0;" :: "n"(n) : "memory")

#define LDSM4(r, a) \
    asm volatile("ldmatrix.sync.aligned.m8n8.x4.shared.b16 {%0,%1,%2,%3}, [%4];" \
        : "=r"((r)[0]), "=r"((r)[1]), "=r"((r)[2]), "=r"((r)[3]) : "r"(a))

#define MMA(d, a, b0, b1) \
    asm volatile("mma.sync.aligned.m16n8k16.row.col.f32.bf16.bf16.f32 " \
        "{%0,%1,%2,%3}, {%4,%5,%6,%7}, {%8,%9}, {%0,%1,%2,%3};" \
        : "+f"((d)[0]), "+f"((d)[1]), "+f"((d)[2]), "+f"((d)[3]) \
        : "r"((a)[0]), "r"((a)[1]), "r"((a)[2]), "r"((a)[3]), "r"(b0), "r"(b1))

__device__ __forceinline__ unsigned pack2(__nv_bfloat16 a, __nv_bfloat16 b) {
    unsigned short x = *reinterpret_cast<unsigned short*>(&a);
    unsigned short y = *reinterpret_cast<unsigned short*>(&b);
    return (unsigned)x | ((unsigned)y << 16);
}
__device__ __forceinline__ void wr_hl4(__nv_bfloat16* H, __nv_bfloat16* L, size_t off, float4 v) {
    __nv_bfloat16 h0 = __float2bfloat16(v.x), h1 = __float2bfloat16(v.y);
    __nv_bfloat16 h2 = __float2bfloat16(v.z), h3 = __float2bfloat16(v.w);
    uint2 hu; hu.x = pack2(h0, h1); hu.y = pack2(h2, h3);
    uint2 lu;
    lu.x = pack2(__float2bfloat16(v.x - __bfloat162float(h0)),
                 __float2bfloat16(v.y - __bfloat162float(h1)));
    lu.y = pack2(__float2bfloat16(v.z - __bfloat162float(h2)),
                 __float2bfloat16(v.w - __bfloat162float(h3)));
    *reinterpret_cast<uint2*>(H + off) = hu;
    *reinterpret_cast<uint2*>(L + off) = lu;
}

// ---------------------------------------------------------------- HMMA GEMM
// D[M,N] = alpha * (Ah@Bh^T + Ah@Bl^T + Al@Bh^T), fp32 accum.
// A: [M][K] row-major bf16 (ldA), B: [N][K] row-major bf16 (ldB).
// Out: Cf (f32) if non-null, else Ch/Cl bf16 hi/lo. ldc elems.
__global__ __launch_bounds__(256, 1) void hmma_gemm(
    const __nv_bfloat16* __restrict__ Ah, const __nv_bfloat16* __restrict__ Al, size_t ldA,
    const __nv_bfloat16* __restrict__ Bh, const __nv_bfloat16* __restrict__ Bl, size_t ldB,
    int K, float alpha,
    float* __restrict__ Cf, __nv_bfloat16* __restrict__ Ch, __nv_bfloat16* __restrict__ Cl,
    int ldc)
{
    extern __shared__ char dynsm[];
    const uint32_t sbase = smem_u32(dynsm);

    const int tid  = threadIdx.x;
    const int wid  = tid >> 5;
    const int lane = tid & 31;
    const int mBase = blockIdx.y * 128;
    const int nBase = blockIdx.x * 128;
    const int nch = K >> 5;               // k chunks of 32

    // warp tile: wm in 0..3 (32 rows), wn in 0..1 (64 cols)
    const int wm = wid & 3, wn = wid >> 2;

    // ---- load geometry: sel 0..3 -> Ah,Al,Bh,Bl; 2 rows/thread, 4 cp16/row
    const int sel  = tid >> 6;
    const int lrow = (tid & 63) * 2;
    const __nv_bfloat16* gsrc;
    size_t gld;
    if (sel == 0)      { gsrc = Ah + (size_t)(mBase + lrow) * ldA; gld = ldA; }
    else if (sel == 1) { gsrc = Al + (size_t)(mBase + lrow) * ldA; gld = ldA; }
    else if (sel == 2) { gsrc = Bh + (size_t)(nBase + lrow) * ldB; gld = ldB; }
    else               { gsrc = Bl + (size_t)(nBase + lrow) * ldB; gld = ldB; }
    const uint32_t sdst0 = sbase + sel * MAT_BYTES + lrow * ROWB;

    #define LOAD_CHUNK(stg, k0) do {                                    \
        const uint32_t _d = sdst0 + (stg) * STG_BYTES;                   \
        const __nv_bfloat16* _s = gsrc + (k0);                           \
        _Pragma("unroll")                                                \
        for (int _j = 0; _j < 4; ++_j) {                                 \
            cp16(_d + _j * 16,        _s + _j * 8);                      \
            cp16(_d + ROWB + _j * 16, _s + gld + _j * 8);                \
        }                                                                \
    } while (0)

    // ---- ldmatrix lane addressing
    const int l15 = lane & 15;
    const int lc8 = (lane >> 4) << 3;     // 0 or 8 (elems)

    float acc[2][8][4];
    #pragma unroll
    for (int i = 0; i < 2; ++i)
        #pragma unroll
        for (int j = 0; j < 8; ++j)
            #pragma unroll
            for (int q = 0; q < 4; ++q) acc[i][j][q] = 0.0f;

    // prologue
    LOAD_CHUNK(0, 0);
    CP_COMMIT();

    for (int i = 0; i < nch; ++i) {
        if (i + 1 < nch) { LOAD_CHUNK((i + 1) & 1, (i + 1) << 5); }
        CP_COMMIT();
        CP_WAIT(1);
        __syncthreads();

        const uint32_t stg = sbase + (i & 1) * STG_BYTES;
        #pragma unroll
        for (int kk = 0; kk < 32; kk += 16) {
            uint32_t ah[2][4], al[2][4], bh[4][4], bl[4][4];
            #pragma unroll
            for (int mi = 0; mi < 2; ++mi) {
                const uint32_t ao = stg + (wm*32 + mi*16 + l15) * ROWB + (kk + lc8) * 2;
                LDSM4(ah[mi], ao);
                LDSM4(al[mi], ao + MAT_BYTES);
            }
            #pragma unroll
            for (int g = 0; g < 4; ++g) {
                const uint32_t bo = stg + 2*MAT_BYTES + (wn*64 + g*16 + l15) * ROWB + (kk + lc8) * 2;
                LDSM4(bh[g], bo);
                LDSM4(bl[g], bo + MAT_BYTES);
            }
            #pragma unroll
            for (int mi = 0; mi < 2; ++mi)
                #pragma unroll
                for (int g = 0; g < 4; ++g) {
                    MMA(acc[mi][2*g+0], ah[mi], bh[g][0], bh[g][2]);
                    MMA(acc[mi][2*g+0], ah[mi], bl[g][0], bl[g][2]);
                    MMA(acc[mi][2*g+0], al[mi], bh[g][0], bh[g][2]);
                    MMA(acc[mi][2*g+1], ah[mi], bh[g][1], bh[g][3]);
                    MMA(acc[mi][2*g+1], ah[mi], bl[g][1], bl[g][3]);
                    MMA(acc[mi][2*g+1], al[mi], bh[g][1], bh[g][3]);
                }
        }
        __syncthreads();
    }

    // ---- epilogue
    const int g4 = lane >> 2, t4 = lane & 3;
    #pragma unroll
    for (int mi = 0; mi < 2; ++mi) {
        #pragma unroll
        for (int nj = 0; nj < 8; ++nj) {
            const int r0 = mBase + wm*32 + mi*16 + g4;
            const int c0 = nBase + wn*64 + nj*8 + t4*2;
            float v0 = acc[mi][nj][0] * alpha, v1 = acc[mi][nj][1] * alpha;
            float v2 = acc[mi][nj][2] * alpha, v3 = acc[mi][nj][3] * alpha;
            if (Cf) {
                *reinterpret_cast<float2*>(Cf + (size_t)r0 * ldc + c0)       = make_float2(v0, v1);
                *reinterpret_cast<float2*>(Cf + (size_t)(r0+8) * ldc + c0)   = make_float2(v2, v3);
            } else {
                __nv_bfloat16 h0 = __float2bfloat16(v0), h1 = __float2bfloat16(v1);
                __nv_bfloat16 h2 = __float2bfloat16(v2), h3 = __float2bfloat16(v3);
                *reinterpret_cast<unsigned*>(Ch + (size_t)r0 * ldc + c0)     = pack2(h0, h1);
                *reinterpret_cast<unsigned*>(Ch + (size_t)(r0+8) * ldc + c0) = pack2(h2, h3);
                *reinterpret_cast<unsigned*>(Cl + (size_t)r0 * ldc + c0) =
                    pack2(__float2bfloat16(v0 - __bfloat162float(h0)),
                          __float2bfloat16(v1 - __bfloat162float(h1)));
                *reinterpret_cast<unsigned*>(Cl + (size_t)(r0+8) * ldc + c0) =
                    pack2(__float2bfloat16(v2 - __bfloat162float(h2)),
                          __float2bfloat16(v3 - __bfloat162float(h3)));
            }
        }
    }
}

// ---------------------------------------------------------------- small kernels
__global__ __launch_bounds__(256) void build_c_split(const float4* __restrict__ s,
                                                     const float4* __restrict__ tg,
                                                     const float4* __restrict__ q)
{
    const size_t i = (size_t)blockIdx.x * blockDim.x + threadIdx.x;   // < 1M
    float4 a = s[i], b = tg[i];
    float4 r; r.x = a.x + b.x; r.y = a.y + b.y; r.z = a.z + b.z; r.w = a.w + b.w;
    wr_hl4(g_ch, g_cl, i * 4, r);
    float4 qq = q[i];
    wr_hl4(g_ch, g_cl, (size_t)BSQ * CDIM + i * 4, qq);
}

__global__ __launch_bounds__(256) void cvt_w(const float4* __restrict__ w,
                                             __nv_bfloat16* __restrict__ H,
                                             __nv_bfloat16* __restrict__ L)
{
    const size_t i = (size_t)blockIdx.x * blockDim.x + threadIdx.x;
    wr_hl4(H, L, i * 4, w[i]);
}

// transpose fp32 [R x C] -> bf16 hi/lo [C x R]
__global__ __launch_bounds__(256) void transpose_cvt(const float* __restrict__ in,
                                                     __nv_bfloat16* __restrict__ oh,
                                                     __nv_bfloat16* __restrict__ ol,
                                                     int R, int C)
{
    __shared__ float t[32][33];
    const int tx = threadIdx.x, ty = threadIdx.y;
    const int x = blockIdx.x * 32 + tx;
    #pragma unroll
    for (int j = 0; j < 4; ++j) {
        const int y = blockIdx.y * 32 + ty + j * 8;
        t[ty + j*8][tx] = in[(size_t)y * C + x];
    }
    __syncthreads();
    const int ox = blockIdx.y * 32 + tx;
    #pragma unroll
    for (int j = 0; j < 4; ++j) {
        const int oy = blockIdx.x * 32 + ty + j * 8;
        float v = t[tx][ty + j*8];
        __nv_bfloat16 h = __float2bfloat16(v);
        oh[(size_t)oy * R + ox] = h;
        ol[(size_t)oy * R + ox] = __float2bfloat16(v - __bfloat162float(h));
    }
}

// softmax over 8192-wide rows of S; emit needed quadrant as bf16 hi/lo
__global__ __launch_bounds__(512) void softmax_fused(const float* __restrict__ S)
{
    const float* p = S + (size_t)blockIdx.x * NTOT;
    const int t = threadIdx.x;
    float v[16];
    float m = -1e30f;
    #pragma unroll
    for (int i = 0; i < 16; ++i) { v[i] = p[t + i * 512]; m = fmaxf(m, v[i]); }

    __shared__ float red[16];
    #pragma unroll
    for (int o = 16; o; o >>= 1) m = fmaxf(m, __shfl_xor_sync(0xffffffffu, m, o));
    if ((t & 31) == 0) red[t >> 5] = m;
    __syncthreads();
    float mm = red[0];
    #pragma unroll
    for (int i = 1; i < 16; ++i) mm = fmaxf(mm, red[i]);

    float sum = 0.0f;
    #pragma unroll
    for (int i = 0; i < 16; ++i) { v[i] = __expf(v[i] - mm); sum += v[i]; }
    #pragma unroll
    for (int o = 16; o; o >>= 1) sum += __shfl_xor_sync(0xffffffffu, sum, o);
    __syncthreads();
    if ((t & 31) == 0) red[t >> 5] = sum;
    __syncthreads();
    float tot = 0.0f;
    #pragma unroll
    for (int i = 0; i < 16; ++i) tot += red[i];
    const float rcp = 1.0f / tot;

    if (blockIdx.x < BSQ) {
        const size_t rb = (size_t)blockIdx.x * BSQ;
        #pragma unroll
        for (int i = 8; i < 16; ++i) {
            const int col = t + (i - 8) * 512;
            float val = v[i] * rcp;
            __nv_bfloat16 h = __float2bfloat16(val);
            g_pcqh[rb + col] = h;
            g_pcql[rb + col] = __float2bfloat16(val - __bfloat162float(h));
        }
    } else {
        const size_t rb = (size_t)(blockIdx.x - BSQ) * BSQ;
        #pragma unroll
        for (int i = 0; i < 8; ++i) {
            const int col = t + i * 512;
            float val = v[i] * rcp;
            __nv_bfloat16 h = __float2bfloat16(val);
            g_pqch[rb + col] = h;
            g_pqcl[rb + col] = __float2bfloat16(val - __bfloat162float(h));
        }
    }
}

// ---------------------------------------------------------------- host
static void run_gemm(const __nv_bfloat16* Ah, const __nv_bfloat16* Al, size_t ldA,
                     const __nv_bfloat16* Bh, const __nv_bfloat16* Bl, size_t ldB,
                     int M, int N, int K, float alpha,
                     float* Cf, __nv_bfloat16* Ch, __nv_bfloat16* Cl, int ldc)
{
    hmma_gemm<<<dim3(N / 128, M / 128), 256, SMEM_GEMM>>>(
        Ah, Al, ldA, Bh, Bl, ldB, K, alpha, Cf, Ch, Cl, ldc);
}

extern "C" void kernel_launch(void* const* d_in, const int* in_sizes, int n_in,
                              void* d_out, int out_size)
{
    const float* query = (const float*)d_in[0];
    const float* s     = (const float*)d_in[1];
    const float* tg    = (const float*)d_in[2];
    const float* Wqkv  = (const float*)d_in[3];
    const float* Wps   = (const float*)d_in[4];
    const float* Wpq   = (const float*)d_in[5];
    float* out = (float*)d_out;

    void* p;
    cudaGetSymbolAddress(&p, g_S);    float* S = (float*)p;
    cudaGetSymbolAddress(&p, g_ch);   __nv_bfloat16* ch = (__nv_bfloat16*)p;
    cudaGetSymbolAddress(&p, g_cl);   __nv_bfloat16* cl = (__nv_bfloat16*)p;
    cudaGetSymbolAddress(&p, g_wqkh); __nv_bfloat16* wqkh = (__nv_bfloat16*)p;
    cudaGetSymbolAddress(&p, g_wqkl); __nv_bfloat16* wqkl = (__nv_bfloat16*)p;
    cudaGetSymbolAddress(&p, g_wpsh); __nv_bfloat16* wpsh = (__nv_bfloat16*)p;
    cudaGetSymbolAddress(&p, g_wpsl); __nv_bfloat16* wpsl = (__nv_bfloat16*)p;
    cudaGetSymbolAddress(&p, g_wpqh); __nv_bfloat16* wpqh = (__nv_bfloat16*)p;
    cudaGetSymbolAddress(&p, g_wpql); __nv_bfloat16* wpql = (__nv_bfloat16*)p;
    cudaGetSymbolAddress(&p, g_qkh);  __nv_bfloat16* qkh = (__nv_bfloat16*)p;
    cudaGetSymbolAddress(&p, g_qkl);  __nv_bfloat16* qkl = (__nv_bfloat16*)p;
    cudaGetSymbolAddress(&p, g_pcqh); __nv_bfloat16* pcqh = (__nv_bfloat16*)p;
    cudaGetSymbolAddress(&p, g_pcql); __nv_bfloat16* pcql = (__nv_bfloat16*)p;
    cudaGetSymbolAddress(&p, g_pqch); __nv_bfloat16* pqch = (__nv_bfloat16*)p;
    cudaGetSymbolAddress(&p, g_pqcl); __nv_bfloat16* pqcl = (__nv_bfloat16*)p;
    cudaGetSymbolAddress(&p, g_qTh);  __nv_bfloat16* qTh = (__nv_bfloat16*)p;
    cudaGetSymbolAddress(&p, g_qTl);  __nv_bfloat16* qTl = (__nv_bfloat16*)p;
    cudaGetSymbolAddress(&p, g_sTh);  __nv_bfloat16* sTh = (__nv_bfloat16*)p;
    cudaGetSymbolAddress(&p, g_sTl);  __nv_bfloat16* sTl = (__nv_bfloat16*)p;
    cudaGetSymbolAddress(&p, g_t0h);  __nv_bfloat16* t0h = (__nv_bfloat16*)p;
    cudaGetSymbolAddress(&p, g_t0l);  __nv_bfloat16* t0l = (__nv_bfloat16*)p;
    cudaGetSymbolAddress(&p, g_t1h);  __nv_bfloat16* t1h = (__nv_bfloat16*)p;
    cudaGetSymbolAddress(&p, g_t1l);  __nv_bfloat16* t1l = (__nv_bfloat16*)p;

    cudaFuncSetAttribute(hmma_gemm, cudaFuncAttributeMaxDynamicSharedMemorySize, SMEM_GEMM);

    // 1) c = [s+TG ; query] -> bf16 hi/lo
    build_c_split<<<(BSQ * CDIM / 4) / 256, 256>>>(
        (const float4*)s, (const float4*)tg, (const float4*)query);

    // 2) weight conversions (v rows of W_qkv are dead)
    cvt_w<<<(QKN * CDIM / 4) / 256, 256>>>((const float4*)Wqkv, wqkh, wqkl);
    cvt_w<<<(HD * HD / 4) / 256, 256>>>((const float4*)Wps, wpsh, wpsl);
    cvt_w<<<(HD * HD / 4) / 256, 256>>>((const float4*)Wpq, wpqh, wpql);

    // 3) transposed bf16 copies of query and s (B operands for attn@V)
    transpose_cvt<<<dim3(CDIM / 32, BSQ / 32), dim3(32, 8)>>>(query, qTh, qTl, BSQ, CDIM);
    transpose_cvt<<<dim3(CDIM / 32, BSQ / 32), dim3(32, 8)>>>(s, sTh, sTl, BSQ, CDIM);

    // 4) qk = SCALE * c @ Wqk^T  -> bf16 hi/lo [8192 x 2048]
    run_gemm(ch, cl, CDIM, wqkh, wqkl, CDIM,
             NTOT, QKN, CDIM, SCALE_F, nullptr, qkh, qkl, QKN);

    // 5) S = q~ @ k~^T (f32) [8192 x 8192]
    run_gemm(qkh, qkl, QKN, qkh + HD, qkl + HD, QKN,
             NTOT, NTOT, CDIM, 1.0f, S, nullptr, nullptr, NTOT);

    // 6) softmax + quadrant split -> bf16 hi/lo
    softmax_fused<<<NTOT, 512>>>(S);

    // 7) t0 = Pcq @ query ; t1 = Pqc @ s  -> bf16 hi/lo [4096 x 1024]
    run_gemm(pcqh, pcql, BSQ, qTh, qTl, BSQ,
             BSQ, HD, BSQ, 1.0f, nullptr, t0h, t0l, HD);
    run_gemm(pqch, pqcl, BSQ, sTh, sTl, BSQ,
             BSQ, HD, BSQ, 1.0f, nullptr, t1h, t1l, HD);

    // 8) x_s = t0 @ Wps^T ; x_q = t1 @ Wpq^T  (f32 into d_out)
    run_gemm(t0h, t0l, HD, wpsh, wpsl, HD,
             BSQ, HD, HD, 1.0f, out, nullptr, nullptr, HD);
    run_gemm(t1h, t1l, HD, wpqh, wpql, HD,
             BSQ, HD, HD, 1.0f, out + (size_t)BSQ * HD, nullptr, nullptr, HD);
}

// round 7
// speedup vs baseline: 1.5286x; 1.0572x over previous
#include <cuda_runtime.h>
#include <cuda_bf16.h>
#include <cstdint>
#include <math.h>

// ---------------------------------------------------------------- constants
#define BSQ   4096
#define CDIM  1024
#define NTOT  8192
#define HD    1024
#define QKN   2048
#define SCALE_F 0.17677669529663687f   // 1024^-0.25

// GEMM config: CTA 128x128, k-chunk 32, 3-stage cp.async pipeline
#define ROWB      80                    // smem row stride bytes (40 bf16)
#define MAT_BYTES (128 * ROWB)          // 10240
#define STG_BYTES (4 * MAT_BYTES)       // Ah,Al,Bh,Bl = 40960
#define NST       3
#define SMEM_GEMM (NST * STG_BYTES)     // 122880

// ---------------------------------------------------------------- scratch
static __device__ float          g_S  [(size_t)NTOT*NTOT];     // 256 MB
static __device__ __nv_bfloat16  g_ch [(size_t)NTOT*CDIM],  g_cl [(size_t)NTOT*CDIM];
static __device__ __nv_bfloat16  g_wqkh[(size_t)QKN*CDIM],  g_wqkl[(size_t)QKN*CDIM];
static __device__ __nv_bfloat16  g_wpsh[(size_t)HD*HD],     g_wpsl[(size_t)HD*HD];
static __device__ __nv_bfloat16  g_wpqh[(size_t)HD*HD],     g_wpql[(size_t)HD*HD];
static __device__ __nv_bfloat16  g_qkh[(size_t)NTOT*QKN],   g_qkl[(size_t)NTOT*QKN];
static __device__ __nv_bfloat16  g_pcqh[(size_t)BSQ*BSQ],   g_pcql[(size_t)BSQ*BSQ];
static __device__ __nv_bfloat16  g_pqch[(size_t)BSQ*BSQ],   g_pqcl[(size_t)BSQ*BSQ];
static __device__ __nv_bfloat16  g_qTh[(size_t)CDIM*BSQ],   g_qTl[(size_t)CDIM*BSQ];
static __device__ __nv_bfloat16  g_sTh[(size_t)CDIM*BSQ],   g_sTl[(size_t)CDIM*BSQ];
static __device__ __nv_bfloat16  g_t0h[(size_t)BSQ*HD],     g_t0l[(size_t)BSQ*HD];
static __device__ __nv_bfloat16  g_t1h[(size_t)BSQ*HD],     g_t1l[(size_t)BSQ*HD];

// ---------------------------------------------------------------- helpers
__device__ __forceinline__ uint32_t smem_u32(const void* p) {
    uint32_t a;
    asm("{ .reg .u64 t; cvta.to.shared.u64 t, %1; cvt.u32.u64 %0, t; }" : "=r"(a) : "l"(p));
    return a;
}
__device__ __forceinline__ void cp16(uint32_t dst, const void* src) {
    asm volatile("cp.async.cg.shared.global [%0], [%1], 16;" :: "r"(dst), "l"(src) : "memory");
}
#define CP_COMMIT() asm volatile("cp.async.commit_group;" ::: "memory")
#define CP_WAIT(n)  asm volatile("cp.async.wait_group %0;" :: "n"(n) : "memory")

#define LDSM4(r, a) \
    asm volatile("ldmatrix.sync.aligned.m8n8.x4.shared.b16 {%0,%1,%2,%3}, [%4];" \
        : "=r"((r)[0]), "=r"((r)[1]), "=r"((r)[2]), "=r"((r)[3]) : "r"(a))

#define MMA(d, a, b0, b1) \
    asm volatile("mma.sync.aligned.m16n8k16.row.col.f32.bf16.bf16.f32 " \
        "{%0,%1,%2,%3}, {%4,%5,%6,%7}, {%8,%9}, {%0,%1,%2,%3};" \
        : "+f"((d)[0]), "+f"((d)[1]), "+f"((d)[2]), "+f"((d)[3]) \
        : "r"((a)[0]), "r"((a)[1]), "r"((a)[2]), "r"((a)[3]), "r"(b0), "r"(b1))

__device__ __forceinline__ unsigned pack2(__nv_bfloat16 a, __nv_bfloat16 b) {
    unsigned short x = *reinterpret_cast<unsigned short*>(&a);
    unsigned short y = *reinterpret_cast<unsigned short*>(&b);
    return (unsigned)x | ((unsigned)y << 16);
}
__device__ __forceinline__ void wr_hl4(__nv_bfloat16* H, __nv_bfloat16* L, size_t off, float4 v) {
    __nv_bfloat16 h0 = __float2bfloat16(v.x), h1 = __float2bfloat16(v.y);
    __nv_bfloat16 h2 = __float2bfloat16(v.z), h3 = __float2bfloat16(v.w);
    uint2 hu; hu.x = pack2(h0, h1); hu.y = pack2(h2, h3);
    uint2 lu;
    lu.x = pack2(__float2bfloat16(v.x - __bfloat162float(h0)),
                 __float2bfloat16(v.y - __bfloat162float(h1)));
    lu.y = pack2(__float2bfloat16(v.z - __bfloat162float(h2)),
                 __float2bfloat16(v.w - __bfloat162float(h3)));
    *reinterpret_cast<uint2*>(H + off) = hu;
    *reinterpret_cast<uint2*>(L + off) = lu;
}

// ---------------------------------------------------------------- HMMA GEMM
// D[M,N] = alpha * (Ah@Bh^T + Ah@Bl^T + Al@Bh^T), fp32 accum.
// A: [M][K] row-major bf16 (ldA), B: [N][K] row-major bf16 (ldB).
// Requires K >= 96 (3-stage prologue), K % 32 == 0.
__global__ __launch_bounds__(256, 1) void hmma_gemm(
    const __nv_bfloat16* __restrict__ Ah, const __nv_bfloat16* __restrict__ Al, size_t ldA,
    const __nv_bfloat16* __restrict__ Bh, const __nv_bfloat16* __restrict__ Bl, size_t ldB,
    int K, float alpha,
    float* __restrict__ Cf, __nv_bfloat16* __restrict__ Ch, __nv_bfloat16* __restrict__ Cl,
    int ldc)
{
    extern __shared__ char dynsm[];
    const uint32_t sbase = smem_u32(dynsm);

    const int tid  = threadIdx.x;
    const int wid  = tid >> 5;
    const int lane = tid & 31;
    const int mBase = blockIdx.y * 128;
    const int nBase = blockIdx.x * 128;
    const int nch = K >> 5;

    // warp tile: wm 0..3 (32 rows), wn 0..1 (64 cols)
    const int wm = wid & 3, wn = wid >> 2;

    // ---- load geometry: sel 0..3 -> Ah,Al,Bh,Bl; 2 rows/thread, 4 cp16/row
    const int sel  = tid >> 6;
    const int lrow = (tid & 63) * 2;
    const __nv_bfloat16* gsrc;
    size_t gld;
    if (sel == 0)      { gsrc = Ah + (size_t)(mBase + lrow) * ldA; gld = ldA; }
    else if (sel == 1) { gsrc = Al + (size_t)(mBase + lrow) * ldA; gld = ldA; }
    else if (sel == 2) { gsrc = Bh + (size_t)(nBase + lrow) * ldB; gld = ldB; }
    else               { gsrc = Bl + (size_t)(nBase + lrow) * ldB; gld = ldB; }
    const uint32_t sdst0 = sbase + sel * MAT_BYTES + lrow * ROWB;

    #define LOAD_CHUNK(stg, k0) do {                                    \
        const uint32_t _d = sdst0 + (stg) * STG_BYTES;                   \
        const __nv_bfloat16* _s = gsrc + (k0);                           \
        _Pragma("unroll")                                                \
        for (int _j = 0; _j < 4; ++_j) {                                 \
            cp16(_d + _j * 16,        _s + _j * 8);                      \
            cp16(_d + ROWB + _j * 16, _s + gld + _j * 8);                \
        }                                                                \
    } while (0)

    const int l15 = lane & 15;
    const int lc8 = (lane >> 4) << 3;

    float acc[2][8][4];
    #pragma unroll
    for (int i = 0; i < 2; ++i)
        #pragma unroll
        for (int j = 0; j < 8; ++j)
            #pragma unroll
            for (int q = 0; q < 4; ++q) acc[i][j][q] = 0.0f;

    // prologue: chunks 0,1 in flight
    LOAD_CHUNK(0, 0);
    CP_COMMIT();
    LOAD_CHUNK(1, 32);
    CP_COMMIT();

    for (int i = 0; i < nch; ++i) {
        CP_WAIT(1);            // chunk i complete (only i+1 may be pending)
        __syncthreads();       // data visible to all; compute(i-1) done by all
        if (i + 2 < nch) { LOAD_CHUNK((i + 2) % NST, (i + 2) << 5); }
        CP_COMMIT();

        const uint32_t stg = sbase + (i % NST) * STG_BYTES;
        #pragma unroll
        for (int kk = 0; kk < 32; kk += 16) {
            uint32_t ah[2][4], al[2][4], bh[4][4], bl[4][4];
            #pragma unroll
            for (int mi = 0; mi < 2; ++mi) {
                const uint32_t ao = stg + (wm*32 + mi*16 + l15) * ROWB + (kk + lc8) * 2;
                LDSM4(ah[mi], ao);
                LDSM4(al[mi], ao + MAT_BYTES);
            }
            #pragma unroll
            for (int g = 0; g < 4; ++g) {
                const uint32_t bo = stg + 2*MAT_BYTES + (wn*64 + g*16 + l15) * ROWB + (kk + lc8) * 2;
                LDSM4(bh[g], bo);
                LDSM4(bl[g], bo + MAT_BYTES);
            }
            // product-major ordering: dependent MMAs on the same acc are 16 apart
            #pragma unroll
            for (int mi = 0; mi < 2; ++mi)
                #pragma unroll
                for (int g = 0; g < 4; ++g) {
                    MMA(acc[mi][2*g+0], ah[mi], bh[g][0], bh[g][2]);
                    MMA(acc[mi][2*g+1], ah[mi], bh[g][1], bh[g][3]);
                }
            #pragma unroll
            for (int mi = 0; mi < 2; ++mi)
                #pragma unroll
                for (int g = 0; g < 4; ++g) {
                    MMA(acc[mi][2*g+0], ah[mi], bl[g][0], bl[g][2]);
                    MMA(acc[mi][2*g+1], ah[mi], bl[g][1], bl[g][3]);
                }
            #pragma unroll
            for (int mi = 0; mi < 2; ++mi)
                #pragma unroll
                for (int g = 0; g < 4; ++g) {
                    MMA(acc[mi][2*g+0], al[mi], bh[g][0], bh[g][2]);
                    MMA(acc[mi][2*g+1], al[mi], bh[g][1], bh[g][3]);
                }
        }
    }

    // ---- epilogue
    const int g4 = lane >> 2, t4 = lane & 3;
    #pragma unroll
    for (int mi = 0; mi < 2; ++mi) {
        #pragma unroll
        for (int nj = 0; nj < 8; ++nj) {
            const int r0 = mBase + wm*32 + mi*16 + g4;
            const int c0 = nBase + wn*64 + nj*8 + t4*2;
            float v0 = acc[mi][nj][0] * alpha, v1 = acc[mi][nj][1] * alpha;
            float v2 = acc[mi][nj][2] * alpha, v3 = acc[mi][nj][3] * alpha;
            if (Cf) {
                *reinterpret_cast<float2*>(Cf + (size_t)r0 * ldc + c0)       = make_float2(v0, v1);
                *reinterpret_cast<float2*>(Cf + (size_t)(r0+8) * ldc + c0)   = make_float2(v2, v3);
            } else {
                __nv_bfloat16 h0 = __float2bfloat16(v0), h1 = __float2bfloat16(v1);
                __nv_bfloat16 h2 = __float2bfloat16(v2), h3 = __float2bfloat16(v3);
                *reinterpret_cast<unsigned*>(Ch + (size_t)r0 * ldc + c0)     = pack2(h0, h1);
                *reinterpret_cast<unsigned*>(Ch + (size_t)(r0+8) * ldc + c0) = pack2(h2, h3);
                *reinterpret_cast<unsigned*>(Cl + (size_t)r0 * ldc + c0) =
                    pack2(__float2bfloat16(v0 - __bfloat162float(h0)),
                          __float2bfloat16(v1 - __bfloat162float(h1)));
                *reinterpret_cast<unsigned*>(Cl + (size_t)(r0+8) * ldc + c0) =
                    pack2(__float2bfloat16(v2 - __bfloat162float(h2)),
                          __float2bfloat16(v3 - __bfloat162float(h3)));
            }
        }
    }
}

// ---------------------------------------------------------------- small kernels
__global__ __launch_bounds__(256) void build_c_split(const float4* __restrict__ s,
                                                     const float4* __restrict__ tg,
                                                     const float4* __restrict__ q)
{
    const size_t i = (size_t)blockIdx.x * blockDim.x + threadIdx.x;
    float4 a = s[i], b = tg[i];
    float4 r; r.x = a.x + b.x; r.y = a.y + b.y; r.z = a.z + b.z; r.w = a.w + b.w;
    wr_hl4(g_ch, g_cl, i * 4, r);
    float4 qq = q[i];
    wr_hl4(g_ch, g_cl, (size_t)BSQ * CDIM + i * 4, qq);
}

__global__ __launch_bounds__(256) void cvt_w(const float4* __restrict__ w,
                                             __nv_bfloat16* __restrict__ H,
                                             __nv_bfloat16* __restrict__ L)
{
    const size_t i = (size_t)blockIdx.x * blockDim.x + threadIdx.x;
    wr_hl4(H, L, i * 4, w[i]);
}

__global__ __launch_bounds__(256) void transpose_cvt(const float* __restrict__ in,
                                                     __nv_bfloat16* __restrict__ oh,
                                                     __nv_bfloat16* __restrict__ ol,
                                                     int R, int C)
{
    __shared__ float t[32][33];
    const int tx = threadIdx.x, ty = threadIdx.y;
    const int x = blockIdx.x * 32 + tx;
    #pragma unroll
    for (int j = 0; j < 4; ++j) {
        const int y = blockIdx.y * 32 + ty + j * 8;
        t[ty + j*8][tx] = in[(size_t)y * C + x];
    }
    __syncthreads();
    const int ox = blockIdx.y * 32 + tx;
    #pragma unroll
    for (int j = 0; j < 4; ++j) {
        const int oy = blockIdx.x * 32 + ty + j * 8;
        float v = t[tx][ty + j*8];
        __nv_bfloat16 h = __float2bfloat16(v);
        oh[(size_t)oy * R + ox] = h;
        ol[(size_t)oy * R + ox] = __float2bfloat16(v - __bfloat162float(h));
    }
}

__global__ __launch_bounds__(512) void softmax_fused(const float* __restrict__ S)
{
    const float* p = S + (size_t)blockIdx.x * NTOT;
    const int t = threadIdx.x;
    float v[16];
    float m = -1e30f;
    #pragma unroll
    for (int i = 0; i < 16; ++i) { v[i] = p[t + i * 512]; m = fmaxf(m, v[i]); }

    __shared__ float red[16];
    #pragma unroll
    for (int o = 16; o; o >>= 1) m = fmaxf(m, __shfl_xor_sync(0xffffffffu, m, o));
    if ((t & 31) == 0) red[t >> 5] = m;
    __syncthreads();
    float mm = red[0];
    #pragma unroll
    for (int i = 1; i < 16; ++i) mm = fmaxf(mm, red[i]);

    float sum = 0.0f;
    #pragma unroll
    for (int i = 0; i < 16; ++i) { v[i] = __expf(v[i] - mm); sum += v[i]; }
    #pragma unroll
    for (int o = 16; o; o >>= 1) sum += __shfl_xor_sync(0xffffffffu, sum, o);
    __syncthreads();
    if ((t & 31) == 0) red[t >> 5] = sum;
    __syncthreads();
    float tot = 0.0f;
    #pragma unroll
    for (int i = 0; i < 16; ++i) tot += red[i];
    const float rcp = 1.0f / tot;

    if (blockIdx.x < BSQ) {
        const size_t rb = (size_t)blockIdx.x * BSQ;
        #pragma unroll
        for (int i = 8; i < 16; ++i) {
            const int col = t + (i - 8) * 512;
            float val = v[i] * rcp;
            __nv_bfloat16 h = __float2bfloat16(val);
            g_pcqh[rb + col] = h;
            g_pcql[rb + col] = __float2bfloat16(val - __bfloat162float(h));
        }
    } else {
        const size_t rb = (size_t)(blockIdx.x - BSQ) * BSQ;
        #pragma unroll
        for (int i = 0; i < 8; ++i) {
            const int col = t + i * 512;
            float val = v[i] * rcp;
            __nv_bfloat16 h = __float2bfloat16(val);
            g_pqch[rb + col] = h;
            g_pqcl[rb + col] = __float2bfloat16(val - __bfloat162float(h));
        }
    }
}

// ---------------------------------------------------------------- host
static void run_gemm(const __nv_bfloat16* Ah, const __nv_bfloat16* Al, size_t ldA,
                     const __nv_bfloat16* Bh, const __nv_bfloat16* Bl, size_t ldB,
                     int M, int N, int K, float alpha,
                     float* Cf, __nv_bfloat16* Ch, __nv_bfloat16* Cl, int ldc)
{
    hmma_gemm<<<dim3(N / 128, M / 128), 256, SMEM_GEMM>>>(
        Ah, Al, ldA, Bh, Bl, ldB, K, alpha, Cf, Ch, Cl, ldc);
}

extern "C" void kernel_launch(void* const* d_in, const int* in_sizes, int n_in,
                              void* d_out, int out_size)
{
    const float* query = (const float*)d_in[0];
    const float* s     = (const float*)d_in[1];
    const float* tg    = (const float*)d_in[2];
    const float* Wqkv  = (const float*)d_in[3];
    const float* Wps   = (const float*)d_in[4];
    const float* Wpq   = (const float*)d_in[5];
    float* out = (float*)d_out;

    void* p;
    cudaGetSymbolAddress(&p, g_S);    float* S = (float*)p;
    cudaGetSymbolAddress(&p, g_ch);   __nv_bfloat16* ch = (__nv_bfloat16*)p;
    cudaGetSymbolAddress(&p, g_cl);   __nv_bfloat16* cl = (__nv_bfloat16*)p;
    cudaGetSymbolAddress(&p, g_wqkh); __nv_bfloat16* wqkh = (__nv_bfloat16*)p;
    cudaGetSymbolAddress(&p, g_wqkl); __nv_bfloat16* wqkl = (__nv_bfloat16*)p;
    cudaGetSymbolAddress(&p, g_wpsh); __nv_bfloat16* wpsh = (__nv_bfloat16*)p;
    cudaGetSymbolAddress(&p, g_wpsl); __nv_bfloat16* wpsl = (__nv_bfloat16*)p;
    cudaGetSymbolAddress(&p, g_wpqh); __nv_bfloat16* wpqh = (__nv_bfloat16*)p;
    cudaGetSymbolAddress(&p, g_wpql); __nv_bfloat16* wpql = (__nv_bfloat16*)p;
    cudaGetSymbolAddress(&p, g_qkh);  __nv_bfloat16* qkh = (__nv_bfloat16*)p;
    cudaGetSymbolAddress(&p, g_qkl);  __nv_bfloat16* qkl = (__nv_bfloat16*)p;
    cudaGetSymbolAddress(&p, g_pcqh); __nv_bfloat16* pcqh = (__nv_bfloat16*)p;
    cudaGetSymbolAddress(&p, g_pcql); __nv_bfloat16* pcql = (__nv_bfloat16*)p;
    cudaGetSymbolAddress(&p, g_pqch); __nv_bfloat16* pqch = (__nv_bfloat16*)p;
    cudaGetSymbolAddress(&p, g_pqcl); __nv_bfloat16* pqcl = (__nv_bfloat16*)p;
    cudaGetSymbolAddress(&p, g_qTh);  __nv_bfloat16* qTh = (__nv_bfloat16*)p;
    cudaGetSymbolAddress(&p, g_qTl);  __nv_bfloat16* qTl = (__nv_bfloat16*)p;
    cudaGetSymbolAddress(&p, g_sTh);  __nv_bfloat16* sTh = (__nv_bfloat16*)p;
    cudaGetSymbolAddress(&p, g_sTl);  __nv_bfloat16* sTl = (__nv_bfloat16*)p;
    cudaGetSymbolAddress(&p, g_t0h);  __nv_bfloat16* t0h = (__nv_bfloat16*)p;
    cudaGetSymbolAddress(&p, g_t0l);  __nv_bfloat16* t0l = (__nv_bfloat16*)p;
    cudaGetSymbolAddress(&p, g_t1h);  __nv_bfloat16* t1h = (__nv_bfloat16*)p;
    cudaGetSymbolAddress(&p, g_t1l);  __nv_bfloat16* t1l = (__nv_bfloat16*)p;

    cudaFuncSetAttribute(hmma_gemm, cudaFuncAttributeMaxDynamicSharedMemorySize, SMEM_GEMM);

    // 1) c = [s+TG ; query] -> bf16 hi/lo
    build_c_split<<<(BSQ * CDIM / 4) / 256, 256>>>(
        (const float4*)s, (const float4*)tg, (const float4*)query);

    // 2) weight conversions (v rows of W_qkv are dead)
    cvt_w<<<(QKN * CDIM / 4) / 256, 256>>>((const float4*)Wqkv, wqkh, wqkl);
    cvt_w<<<(HD * HD / 4) / 256, 256>>>((const float4*)Wps, wpsh, wpsl);
    cvt_w<<<(HD * HD / 4) / 256, 256>>>((const float4*)Wpq, wpqh, wpql);

    // 3) transposed bf16 copies of query and s (B operands for attn@V)
    transpose_cvt<<<dim3(CDIM / 32, BSQ / 32), dim3(32, 8)>>>(query, qTh, qTl, BSQ, CDIM);
    transpose_cvt<<<dim3(CDIM / 32, BSQ / 32), dim3(32, 8)>>>(s, sTh, sTl, BSQ, CDIM);

    // 4) qk = SCALE * c @ Wqk^T  -> bf16 hi/lo [8192 x 2048]
    run_gemm(ch, cl, CDIM, wqkh, wqkl, CDIM,
             NTOT, QKN, CDIM, SCALE_F, nullptr, qkh, qkl, QKN);

    // 5) S = q~ @ k~^T (f32) [8192 x 8192]
    run_gemm(qkh, qkl, QKN, qkh + HD, qkl + HD, QKN,
             NTOT, NTOT, CDIM, 1.0f, S, nullptr, nullptr, NTOT);

    // 6) softmax + quadrant split -> bf16 hi/lo
    softmax_fused<<<NTOT, 512>>>(S);

    // 7) t0 = Pcq @ query ; t1 = Pqc @ s  -> bf16 hi/lo [4096 x 1024]
    run_gemm(pcqh, pcql, BSQ, qTh, qTl, BSQ,
             BSQ, HD, BSQ, 1.0f, nullptr, t0h, t0l, HD);
    run_gemm(pqch, pqcl, BSQ, sTh, sTl, BSQ,
             BSQ, HD, BSQ, 1.0f, nullptr, t1h, t1l, HD);

    // 8) x_s = t0 @ Wps^T ; x_q = t1 @ Wpq^T  (f32 into d_out)
    run_gemm(t0h, t0l, HD, wpsh, wpsl, HD,
             BSQ, HD, HD, 1.0f, out, nullptr, nullptr, HD);
    run_gemm(t1h, t1l, HD, wpqh, wpql, HD,
             BSQ, HD, HD, 1.0f, out + (size_t)BSQ * HD, nullptr, nullptr, HD);
}

// round 8
// speedup vs baseline: 1.5481x; 1.0128x over previous
#include <cuda_runtime.h>
#include <cuda_bf16.h>
#include <cstdint>
#include <math.h>

// ---------------------------------------------------------------- constants
#define BSQ   4096
#define CDIM  1024
#define NTOT  8192
#define HD    1024
#define SCALE2_F 0.03125f              // (1024^-0.25)^2 = 1/32

// GEMM config: CTA 128x128, k-chunk 64, 3-stage cp.async pipeline
#define ROWB      144                  // smem row stride bytes (64 bf16 data + pad)
#define MAT_BYTES (128 * ROWB)         // 18432
#define STG_BYTES (4 * MAT_BYTES)      // Ah,Al,Bh,Bl = 73728
#define NST       3
#define SMEM_GEMM (NST * STG_BYTES)    // 221184

// ---------------------------------------------------------------- scratch
static __device__ float          g_S  [(size_t)NTOT*NTOT];     // 256 MB
static __device__ __nv_bfloat16  g_ch [(size_t)NTOT*CDIM],  g_cl [(size_t)NTOT*CDIM];
static __device__ __nv_bfloat16  g_wqTh[(size_t)CDIM*HD],   g_wqTl[(size_t)CDIM*HD];
static __device__ __nv_bfloat16  g_wkTh[(size_t)CDIM*HD],   g_wkTl[(size_t)CDIM*HD];
static __device__ __nv_bfloat16  g_mwth[(size_t)HD*CDIM],   g_mwtl[(size_t)HD*CDIM];
static __device__ __nv_bfloat16  g_zh [(size_t)NTOT*HD],    g_zl [(size_t)NTOT*HD];
static __device__ __nv_bfloat16  g_wpsh[(size_t)HD*HD],     g_wpsl[(size_t)HD*HD];
static __device__ __nv_bfloat16  g_wpqh[(size_t)HD*HD],     g_wpql[(size_t)HD*HD];
static __device__ __nv_bfloat16  g_pcqh[(size_t)BSQ*BSQ],   g_pcql[(size_t)BSQ*BSQ];
static __device__ __nv_bfloat16  g_pqch[(size_t)BSQ*BSQ],   g_pqcl[(size_t)BSQ*BSQ];
static __device__ __nv_bfloat16  g_qTh[(size_t)CDIM*BSQ],   g_qTl[(size_t)CDIM*BSQ];
static __device__ __nv_bfloat16  g_sTh[(size_t)CDIM*BSQ],   g_sTl[(size_t)CDIM*BSQ];
static __device__ __nv_bfloat16  g_t0h[(size_t)BSQ*HD],     g_t0l[(size_t)BSQ*HD];
static __device__ __nv_bfloat16  g_t1h[(size_t)BSQ*HD],     g_t1l[(size_t)BSQ*HD];

// ---------------------------------------------------------------- helpers
__device__ __forceinline__ uint32_t smem_u32(const void* p) {
    uint32_t a;
    asm("{ .reg .u64 t; cvta.to.shared.u64 t, %1; cvt.u32.u64 %0, t; }" : "=r"(a) : "l"(p));
    return a;
}
__device__ __forceinline__ void cp16(uint32_t dst, const void* src) {
    asm volatile("cp.async.cg.shared.global [%0], [%1], 16;" :: "r"(dst), "l"(src) : "memory");
}
#define CP_COMMIT() asm volatile("cp.async.commit_group;" ::: "memory")
#define CP_WAIT(n)  asm volatile("cp.async.wait_group %0;" :: "n"(n) : "memory")

#define LDSM4(r, a) \
    asm volatile("ldmatrix.sync.aligned.m8n8.x4.shared.b16 {%0,%1,%2,%3}, [%4];" \
        : "=r"((r)[0]), "=r"((r)[1]), "=r"((r)[2]), "=r"((r)[3]) : "r"(a))

#define MMA(d, a, b0, b1) \
    asm volatile("mma.sync.aligned.m16n8k16.row.col.f32.bf16.bf16.f32 " \
        "{%0,%1,%2,%3}, {%4,%5,%6,%7}, {%8,%9}, {%0,%1,%2,%3};" \
        : "+f"((d)[0]), "+f"((d)[1]), "+f"((d)[2]), "+f"((d)[3]) \
        : "r"((a)[0]), "r"((a)[1]), "r"((a)[2]), "r"((a)[3]), "r"(b0), "r"(b1))

__device__ __forceinline__ unsigned pack2(__nv_bfloat16 a, __nv_bfloat16 b) {
    unsigned short x = *reinterpret_cast<unsigned short*>(&a);
    unsigned short y = *reinterpret_cast<unsigned short*>(&b);
    return (unsigned)x | ((unsigned)y << 16);
}
__device__ __forceinline__ void wr_hl4(__nv_bfloat16* H, __nv_bfloat16* L, size_t off, float4 v) {
    __nv_bfloat16 h0 = __float2bfloat16(v.x), h1 = __float2bfloat16(v.y);
    __nv_bfloat16 h2 = __float2bfloat16(v.z), h3 = __float2bfloat16(v.w);
    uint2 hu; hu.x = pack2(h0, h1); hu.y = pack2(h2, h3);
    uint2 lu;
    lu.x = pack2(__float2bfloat16(v.x - __bfloat162float(h0)),
                 __float2bfloat16(v.y - __bfloat162float(h1)));
    lu.y = pack2(__float2bfloat16(v.z - __bfloat162float(h2)),
                 __float2bfloat16(v.w - __bfloat162float(h3)));
    *reinterpret_cast<uint2*>(H + off) = hu;
    *reinterpret_cast<uint2*>(L + off) = lu;
}

// ---------------------------------------------------------------- HMMA GEMM
// D[M,N] = alpha * (Ah@Bh^T + Ah@Bl^T + Al@Bh^T), fp32 accum.
// A: [M][K] row-major bf16 (ldA), B: [N][K] row-major bf16 (ldB).
// Requires K % 64 == 0, K >= 128.
__global__ __launch_bounds__(256, 1) void hmma_gemm(
    const __nv_bfloat16* __restrict__ Ah, const __nv_bfloat16* __restrict__ Al, size_t ldA,
    const __nv_bfloat16* __restrict__ Bh, const __nv_bfloat16* __restrict__ Bl, size_t ldB,
    int K, float alpha,
    float* __restrict__ Cf, __nv_bfloat16* __restrict__ Ch, __nv_bfloat16* __restrict__ Cl,
    int ldc)
{
    extern __shared__ char dynsm[];
    const uint32_t sbase = smem_u32(dynsm);

    const int tid  = threadIdx.x;
    const int wid  = tid >> 5;
    const int lane = tid & 31;
    const int mBase = blockIdx.y * 128;
    const int nBase = blockIdx.x * 128;
    const int nch = K >> 6;

    const int wm = wid & 3, wn = wid >> 2;

    // ---- load geometry: sel 0..3 -> Ah,Al,Bh,Bl; 2 rows/thread, 8 cp16/row
    const int sel  = tid >> 6;
    const int lrow = (tid & 63) * 2;
    const __nv_bfloat16* gsrc;
    size_t gld;
    if (sel == 0)      { gsrc = Ah + (size_t)(mBase + lrow) * ldA; gld = ldA; }
    else if (sel == 1) { gsrc = Al + (size_t)(mBase + lrow) * ldA; gld = ldA; }
    else if (sel == 2) { gsrc = Bh + (size_t)(nBase + lrow) * ldB; gld = ldB; }
    else               { gsrc = Bl + (size_t)(nBase + lrow) * ldB; gld = ldB; }
    const uint32_t sdst0 = sbase + sel * MAT_BYTES + lrow * ROWB;

    #define LOAD_CHUNK(stg, k0) do {                                    \
        const uint32_t _d = sdst0 + (stg) * STG_BYTES;                   \
        const __nv_bfloat16* _s = gsrc + (k0);                           \
        _Pragma("unroll")                                                \
        for (int _j = 0; _j < 8; ++_j) {                                 \
            cp16(_d + _j * 16,        _s + _j * 8);                      \
            cp16(_d + ROWB + _j * 16, _s + gld + _j * 8);                \
        }                                                                \
    } while (0)

    const int l15 = lane & 15;
    const int lc8 = (lane >> 4) << 3;

    float acc[2][8][4];
    #pragma unroll
    for (int i = 0; i < 2; ++i)
        #pragma unroll
        for (int j = 0; j < 8; ++j)
            #pragma unroll
            for (int q = 0; q < 4; ++q) acc[i][j][q] = 0.0f;

    // prologue: chunks 0,1 in flight
    LOAD_CHUNK(0, 0);
    CP_COMMIT();
    LOAD_CHUNK(1, 64);
    CP_COMMIT();

    for (int i = 0; i < nch; ++i) {
        CP_WAIT(1);            // chunk i complete
        __syncthreads();       // all warps done with chunk i-1 (stage (i+2)%3)
        if (i + 2 < nch) { LOAD_CHUNK((i + 2) % NST, (i + 2) << 6); }
        CP_COMMIT();

        const uint32_t stg = sbase + (i % NST) * STG_BYTES;
        #pragma unroll
        for (int kk = 0; kk < 64; kk += 16) {
            uint32_t ah[2][4], al[2][4], bh[4][4], bl[4][4];
            #pragma unroll
            for (int mi = 0; mi < 2; ++mi) {
                const uint32_t ao = stg + (wm*32 + mi*16 + l15) * ROWB + (kk + lc8) * 2;
                LDSM4(ah[mi], ao);
                LDSM4(al[mi], ao + MAT_BYTES);
            }
            #pragma unroll
            for (int g = 0; g < 4; ++g) {
                const uint32_t bo = stg + 2*MAT_BYTES + (wn*64 + g*16 + l15) * ROWB + (kk + lc8) * 2;
                LDSM4(bh[g], bo);
                LDSM4(bl[g], bo + MAT_BYTES);
            }
            // product-major: dependent MMAs on same acc are 16 apart
            #pragma unroll
            for (int mi = 0; mi < 2; ++mi)
                #pragma unroll
                for (int g = 0; g < 4; ++g) {
                    MMA(acc[mi][2*g+0], ah[mi], bh[g][0], bh[g][2]);
                    MMA(acc[mi][2*g+1], ah[mi], bh[g][1], bh[g][3]);
                }
            #pragma unroll
            for (int mi = 0; mi < 2; ++mi)
                #pragma unroll
                for (int g = 0; g < 4; ++g) {
                    MMA(acc[mi][2*g+0], ah[mi], bl[g][0], bl[g][2]);
                    MMA(acc[mi][2*g+1], ah[mi], bl[g][1], bl[g][3]);
                }
            #pragma unroll
            for (int mi = 0; mi < 2; ++mi)
                #pragma unroll
                for (int g = 0; g < 4; ++g) {
                    MMA(acc[mi][2*g+0], al[mi], bh[g][0], bh[g][2]);
                    MMA(acc[mi][2*g+1], al[mi], bh[g][1], bh[g][3]);
                }
        }
    }

    // ---- epilogue
    const int g4 = lane >> 2, t4 = lane & 3;
    #pragma unroll
    for (int mi = 0; mi < 2; ++mi) {
        #pragma unroll
        for (int nj = 0; nj < 8; ++nj) {
            const int r0 = mBase + wm*32 + mi*16 + g4;
            const int c0 = nBase + wn*64 + nj*8 + t4*2;
            float v0 = acc[mi][nj][0] * alpha, v1 = acc[mi][nj][1] * alpha;
            float v2 = acc[mi][nj][2] * alpha, v3 = acc[mi][nj][3] * alpha;
            if (Cf) {
                *reinterpret_cast<float2*>(Cf + (size_t)r0 * ldc + c0)       = make_float2(v0, v1);
                *reinterpret_cast<float2*>(Cf + (size_t)(r0+8) * ldc + c0)   = make_float2(v2, v3);
            } else {
                __nv_bfloat16 h0 = __float2bfloat16(v0), h1 = __float2bfloat16(v1);
                __nv_bfloat16 h2 = __float2bfloat16(v2), h3 = __float2bfloat16(v3);
                *reinterpret_cast<unsigned*>(Ch + (size_t)r0 * ldc + c0)     = pack2(h0, h1);
                *reinterpret_cast<unsigned*>(Ch + (size_t)(r0+8) * ldc + c0) = pack2(h2, h3);
                *reinterpret_cast<unsigned*>(Cl + (size_t)r0 * ldc + c0) =
                    pack2(__float2bfloat16(v0 - __bfloat162float(h0)),
                          __float2bfloat16(v1 - __bfloat162float(h1)));
                *reinterpret_cast<unsigned*>(Cl + (size_t)(r0+8) * ldc + c0) =
                    pack2(__float2bfloat16(v2 - __bfloat162float(h2)),
                          __float2bfloat16(v3 - __bfloat162float(h3)));
            }
        }
    }
}

// ---------------------------------------------------------------- small kernels
__global__ __launch_bounds__(256) void build_c_split(const float4* __restrict__ s,
                                                     const float4* __restrict__ tg,
                                                     const float4* __restrict__ q)
{
    const size_t i = (size_t)blockIdx.x * blockDim.x + threadIdx.x;
    float4 a = s[i], b = tg[i];
    float4 r; r.x = a.x + b.x; r.y = a.y + b.y; r.z = a.z + b.z; r.w = a.w + b.w;
    wr_hl4(g_ch, g_cl, i * 4, r);
    float4 qq = q[i];
    wr_hl4(g_ch, g_cl, (size_t)BSQ * CDIM + i * 4, qq);
}

__global__ __launch_bounds__(256) void cvt_w(const float4* __restrict__ w,
                                             __nv_bfloat16* __restrict__ H,
                                             __nv_bfloat16* __restrict__ L)
{
    const size_t i = (size_t)blockIdx.x * blockDim.x + threadIdx.x;
    wr_hl4(H, L, i * 4, w[i]);
}

// transpose fp32 [R x C] -> bf16 hi/lo [C x R]
__global__ __launch_bounds__(256) void transpose_cvt(const float* __restrict__ in,
                                                     __nv_bfloat16* __restrict__ oh,
                                                     __nv_bfloat16* __restrict__ ol,
                                                     int R, int C)
{
    __shared__ float t[32][33];
    const int tx = threadIdx.x, ty = threadIdx.y;
    const int x = blockIdx.x * 32 + tx;
    #pragma unroll
    for (int j = 0; j < 4; ++j) {
        const int y = blockIdx.y * 32 + ty + j * 8;
        t[ty + j*8][tx] = in[(size_t)y * C + x];
    }
    __syncthreads();
    const int ox = blockIdx.y * 32 + tx;
    #pragma unroll
    for (int j = 0; j < 4; ++j) {
        const int oy = blockIdx.x * 32 + ty + j * 8;
        float v = t[tx][ty + j*8];
        __nv_bfloat16 h = __float2bfloat16(v);
        oh[(size_t)oy * R + ox] = h;
        ol[(size_t)oy * R + ox] = __float2bfloat16(v - __bfloat162float(h));
    }
}

__global__ __launch_bounds__(512) void softmax_fused(const float* __restrict__ S)
{
    const float* p = S + (size_t)blockIdx.x * NTOT;
    const int t = threadIdx.x;
    float v[16];
    float m = -1e30f;
    #pragma unroll
    for (int i = 0; i < 16; ++i) { v[i] = p[t + i * 512]; m = fmaxf(m, v[i]); }

    __shared__ float red[16];
    #pragma unroll
    for (int o = 16; o; o >>= 1) m = fmaxf(m, __shfl_xor_sync(0xffffffffu, m, o));
    if ((t & 31) == 0) red[t >> 5] = m;
    __syncthreads();
    float mm = red[0];
    #pragma unroll
    for (int i = 1; i < 16; ++i) mm = fmaxf(mm, red[i]);

    float sum = 0.0f;
    #pragma unroll
    for (int i = 0; i < 16; ++i) { v[i] = __expf(v[i] - mm); sum += v[i]; }
    #pragma unroll
    for (int o = 16; o; o >>= 1) sum += __shfl_xor_sync(0xffffffffu, sum, o);
    __syncthreads();
    if ((t & 31) == 0) red[t >> 5] = sum;
    __syncthreads();
    float tot = 0.0f;
    #pragma unroll
    for (int i = 0; i < 16; ++i) tot += red[i];
    const float rcp = 1.0f / tot;

    if (blockIdx.x < BSQ) {
        const size_t rb = (size_t)blockIdx.x * BSQ;
        #pragma unroll
        for (int i = 8; i < 16; ++i) {
            const int col = t + (i - 8) * 512;
            float val = v[i] * rcp;
            __nv_bfloat16 h = __float2bfloat16(val);
            g_pcqh[rb + col] = h;
            g_pcql[rb + col] = __float2bfloat16(val - __bfloat162float(h));
        }
    } else {
        const size_t rb = (size_t)(blockIdx.x - BSQ) * BSQ;
        #pragma unroll
        for (int i = 0; i < 8; ++i) {
            const int col = t + i * 512;
            float val = v[i] * rcp;
            __nv_bfloat16 h = __float2bfloat16(val);
            g_pqch[rb + col] = h;
            g_pqcl[rb + col] = __float2bfloat16(val - __bfloat162float(h));
        }
    }
}

// ---------------------------------------------------------------- host
static void run_gemm(const __nv_bfloat16* Ah, const __nv_bfloat16* Al, size_t ldA,
                     const __nv_bfloat16* Bh, const __nv_bfloat16* Bl, size_t ldB,
                     int M, int N, int K, float alpha,
                     float* Cf, __nv_bfloat16* Ch, __nv_bfloat16* Cl, int ldc)
{
    hmma_gemm<<<dim3(N / 128, M / 128), 256, SMEM_GEMM>>>(
        Ah, Al, ldA, Bh, Bl, ldB, K, alpha, Cf, Ch, Cl, ldc);
}

extern "C" void kernel_launch(void* const* d_in, const int* in_sizes, int n_in,
                              void* d_out, int out_size)
{
    const float* query = (const float*)d_in[0];
    const float* s     = (const float*)d_in[1];
    const float* tg    = (const float*)d_in[2];
    const float* Wqkv  = (const float*)d_in[3];
    const float* Wps   = (const float*)d_in[4];
    const float* Wpq   = (const float*)d_in[5];
    float* out = (float*)d_out;

    void* p;
    cudaGetSymbolAddress(&p, g_S);    float* S = (float*)p;
    cudaGetSymbolAddress(&p, g_ch);   __nv_bfloat16* ch = (__nv_bfloat16*)p;
    cudaGetSymbolAddress(&p, g_cl);   __nv_bfloat16* cl = (__nv_bfloat16*)p;
    cudaGetSymbolAddress(&p, g_wqTh); __nv_bfloat16* wqTh = (__nv_bfloat16*)p;
    cudaGetSymbolAddress(&p, g_wqTl); __nv_bfloat16* wqTl = (__nv_bfloat16*)p;
    cudaGetSymbolAddress(&p, g_wkTh); __nv_bfloat16* wkTh = (__nv_bfloat16*)p;
    cudaGetSymbolAddress(&p, g_wkTl); __nv_bfloat16* wkTl = (__nv_bfloat16*)p;
    cudaGetSymbolAddress(&p, g_mwth); __nv_bfloat16* mwth = (__nv_bfloat16*)p;
    cudaGetSymbolAddress(&p, g_mwtl); __nv_bfloat16* mwtl = (__nv_bfloat16*)p;
    cudaGetSymbolAddress(&p, g_zh);   __nv_bfloat16* zh = (__nv_bfloat16*)p;
    cudaGetSymbolAddress(&p, g_zl);   __nv_bfloat16* zl = (__nv_bfloat16*)p;
    cudaGetSymbolAddress(&p, g_wpsh); __nv_bfloat16* wpsh = (__nv_bfloat16*)p;
    cudaGetSymbolAddress(&p, g_wpsl); __nv_bfloat16* wpsl = (__nv_bfloat16*)p;
    cudaGetSymbolAddress(&p, g_wpqh); __nv_bfloat16* wpqh = (__nv_bfloat16*)p;
    cudaGetSymbolAddress(&p, g_wpql); __nv_bfloat16* wpql = (__nv_bfloat16*)p;
    cudaGetSymbolAddress(&p, g_pcqh); __nv_bfloat16* pcqh = (__nv_bfloat16*)p;
    cudaGetSymbolAddress(&p, g_pcql); __nv_bfloat16* pcql = (__nv_bfloat16*)p;
    cudaGetSymbolAddress(&p, g_pqch); __nv_bfloat16* pqch = (__nv_bfloat16*)p;
    cudaGetSymbolAddress(&p, g_pqcl); __nv_bfloat16* pqcl = (__nv_bfloat16*)p;
    cudaGetSymbolAddress(&p, g_qTh);  __nv_bfloat16* qTh = (__nv_bfloat16*)p;
    cudaGetSymbolAddress(&p, g_qTl);  __nv_bfloat16* qTl = (__nv_bfloat16*)p;
    cudaGetSymbolAddress(&p, g_sTh);  __nv_bfloat16* sTh = (__nv_bfloat16*)p;
    cudaGetSymbolAddress(&p, g_sTl);  __nv_bfloat16* sTl = (__nv_bfloat16*)p;
    cudaGetSymbolAddress(&p, g_t0h);  __nv_bfloat16* t0h = (__nv_bfloat16*)p;
    cudaGetSymbolAddress(&p, g_t0l);  __nv_bfloat16* t0l = (__nv_bfloat16*)p;
    cudaGetSymbolAddress(&p, g_t1h);  __nv_bfloat16* t1h = (__nv_bfloat16*)p;
    cudaGetSymbolAddress(&p, g_t1l);  __nv_bfloat16* t1l = (__nv_bfloat16*)p;

    cudaFuncSetAttribute(hmma_gemm, cudaFuncAttributeMaxDynamicSharedMemorySize, SMEM_GEMM);

    // 1) c = [s+TG ; query] -> bf16 hi/lo
    build_c_split<<<(BSQ * CDIM / 4) / 256, 256>>>(
        (const float4*)s, (const float4*)tg, (const float4*)query);

    // 2) projection weight conversions
    cvt_w<<<(HD * HD / 4) / 256, 256>>>((const float4*)Wps, wpsh, wpsl);
    cvt_w<<<(HD * HD / 4) / 256, 256>>>((const float4*)Wpq, wpqh, wpql);

    // 3) transposes: query^T, s^T (attn@V B operands), Wq^T, Wk^T
    transpose_cvt<<<dim3(CDIM / 32, BSQ / 32), dim3(32, 8)>>>(query, qTh, qTl, BSQ, CDIM);
    transpose_cvt<<<dim3(CDIM / 32, BSQ / 32), dim3(32, 8)>>>(s, sTh, sTl, BSQ, CDIM);
    transpose_cvt<<<dim3(CDIM / 32, HD / 32), dim3(32, 8)>>>(Wqkv, wqTh, wqTl, HD, CDIM);
    transpose_cvt<<<dim3(CDIM / 32, HD / 32), dim3(32, 8)>>>(Wqkv + (size_t)HD * CDIM,
                                                             wkTh, wkTl, HD, CDIM);

    // 4) MwT = SCALE^2 * Wk^T @ Wq  -> bf16 hi/lo [1024 x 1024]
    //    MwT[d][c] = SCALE2 * sum_i WkT[d][i] * WqT[c][i]
    run_gemm(wkTh, wkTl, HD, wqTh, wqTl, HD,
             CDIM, CDIM, HD, SCALE2_F, nullptr, mwth, mwtl, CDIM);

    // 5) Z = c @ MwT^T  -> bf16 hi/lo [8192 x 1024]
    //    Z[m][d] = sum_c c[m][c] * MwT[d][c]
    run_gemm(ch, cl, CDIM, mwth, mwtl, CDIM,
             NTOT, HD, CDIM, 1.0f, nullptr, zh, zl, HD);

    // 6) S = Z @ c^T (f32) [8192 x 8192];  S[m][n] = sum_d Z[m][d] c[n][d]
    run_gemm(zh, zl, HD, ch, cl, CDIM,
             NTOT, NTOT, HD, 1.0f, S, nullptr, nullptr, NTOT);

    // 7) softmax + quadrant split -> bf16 hi/lo
    softmax_fused<<<NTOT, 512>>>(S);

    // 8) t0 = Pcq @ query ; t1 = Pqc @ s  -> bf16 hi/lo [4096 x 1024]
    run_gemm(pcqh, pcql, BSQ, qTh, qTl, BSQ,
             BSQ, HD, BSQ, 1.0f, nullptr, t0h, t0l, HD);
    run_gemm(pqch, pqcl, BSQ, sTh, sTl, BSQ,
             BSQ, HD, BSQ, 1.0f, nullptr, t1h, t1l, HD);

    // 9) x_s = t0 @ Wps^T ; x_q = t1 @ Wpq^T  (f32 into d_out)
    run_gemm(t0h, t0l, HD, wpsh, wpsl, HD,
             BSQ, HD, HD, 1.0f, out, nullptr, nullptr, HD);
    run_gemm(t1h, t1l, HD, wpqh, wpql, HD,
             BSQ, HD, HD, 1.0f, out + (size_t)BSQ * HD, nullptr, nullptr, HD);
}

// round 9
// speedup vs baseline: 1.8186x; 1.1747x over previous
#include <cuda_runtime.h>
#include <cuda_fp16.h>
#include <cstdint>
#include <math.h>

// ---------------------------------------------------------------- constants
#define BSQ   4096
#define CDIM  1024
#define NTOT  8192
#define HD    1024
#define SCALE2_F 0.03125f              // (1024^-0.25)^2 = 1/32

// GEMM config: CTA 128x128, k-chunk 64, 3-stage cp.async pipeline
#define ROWB      144                  // smem row stride bytes (64 f16 data + pad)
#define MAT_BYTES (128 * ROWB)         // 18432
#define STG_BYTES (4 * MAT_BYTES)      // Ah,Al,Bh,Bl = 73728
#define NST       3
#define SMEM_GEMM (NST * STG_BYTES)    // 221184

// ---------------------------------------------------------------- scratch
static __device__ float   g_S  [(size_t)NTOT*NTOT];            // 256 MB
static __device__ __half  g_ch [(size_t)NTOT*CDIM],  g_cl [(size_t)NTOT*CDIM];
static __device__ __half  g_wqTh[(size_t)CDIM*HD],   g_wqTl[(size_t)CDIM*HD];
static __device__ __half  g_wkTh[(size_t)CDIM*HD],   g_wkTl[(size_t)CDIM*HD];
static __device__ __half  g_mwth[(size_t)HD*CDIM],   g_mwtl[(size_t)HD*CDIM];
static __device__ __half  g_zh [(size_t)NTOT*HD],    g_zl [(size_t)NTOT*HD];
static __device__ __half  g_wpsh[(size_t)HD*HD],     g_wpsl[(size_t)HD*HD];
static __device__ __half  g_wpqh[(size_t)HD*HD],     g_wpql[(size_t)HD*HD];
static __device__ __half  g_pcqh[(size_t)BSQ*BSQ],   g_pcql[(size_t)BSQ*BSQ];
static __device__ __half  g_pqch[(size_t)BSQ*BSQ],   g_pqcl[(size_t)BSQ*BSQ];
static __device__ __half  g_qTh[(size_t)CDIM*BSQ],   g_qTl[(size_t)CDIM*BSQ];
static __device__ __half  g_sTh[(size_t)CDIM*BSQ],   g_sTl[(size_t)CDIM*BSQ];
static __device__ __half  g_t0h[(size_t)BSQ*HD],     g_t0l[(size_t)BSQ*HD];
static __device__ __half  g_t1h[(size_t)BSQ*HD],     g_t1l[(size_t)BSQ*HD];

// ---------------------------------------------------------------- helpers
__device__ __forceinline__ uint32_t smem_u32(const void* p) {
    uint32_t a;
    asm("{ .reg .u64 t; cvta.to.shared.u64 t, %1; cvt.u32.u64 %0, t; }" : "=r"(a) : "l"(p));
    return a;
}
__device__ __forceinline__ void cp16(uint32_t dst, const void* src) {
    asm volatile("cp.async.cg.shared.global [%0], [%1], 16;" :: "r"(dst), "l"(src) : "memory");
}
#define CP_COMMIT() asm volatile("cp.async.commit_group;" ::: "memory")
#define CP_WAIT(n)  asm volatile("cp.async.wait_group %0;" :: "n"(n) : "memory")

#define LDSM4(r, a) \
    asm volatile("ldmatrix.sync.aligned.m8n8.x4.shared.b16 {%0,%1,%2,%3}, [%4];" \
        : "=r"((r)[0]), "=r"((r)[1]), "=r"((r)[2]), "=r"((r)[3]) : "r"(a))

#define MMA(d, a, b0, b1) \
    asm volatile("mma.sync.aligned.m16n8k16.row.col.f32.f16.f16.f32 " \
        "{%0,%1,%2,%3}, {%4,%5,%6,%7}, {%8,%9}, {%0,%1,%2,%3};" \
        : "+f"((d)[0]), "+f"((d)[1]), "+f"((d)[2]), "+f"((d)[3]) \
        : "r"((a)[0]), "r"((a)[1]), "r"((a)[2]), "r"((a)[3]), "r"(b0), "r"(b1))

__device__ __forceinline__ unsigned pack2(__half a, __half b) {
    unsigned short x = *reinterpret_cast<unsigned short*>(&a);
    unsigned short y = *reinterpret_cast<unsigned short*>(&b);
    return (unsigned)x | ((unsigned)y << 16);
}
__device__ __forceinline__ void wr_hl4(__half* H, __half* L, size_t off, float4 v) {
    __half h0 = __float2half(v.x), h1 = __float2half(v.y);
    __half h2 = __float2half(v.z), h3 = __float2half(v.w);
    uint2 hu; hu.x = pack2(h0, h1); hu.y = pack2(h2, h3);
    uint2 lu;
    lu.x = pack2(__float2half(v.x - __half2float(h0)),
                 __float2half(v.y - __half2float(h1)));
    lu.y = pack2(__float2half(v.z - __half2float(h2)),
                 __float2half(v.w - __half2float(h3)));
    *reinterpret_cast<uint2*>(H + off) = hu;
    *reinterpret_cast<uint2*>(L + off) = lu;
}

// ---------------------------------------------------------------- HMMA GEMM
// NPROD==3: D = alpha*(Ah@Bh^T + Ah@Bl^T + Al@Bh^T)   (~2^-23 eff. precision)
// NPROD==2: D = alpha*(Ah@Bh^T + Ah@Bl^T)             (A rounded to f16, ~2^-12)
// A: [M][K] row-major f16 (ldA), B: [N][K] row-major f16 (ldB).
// K % 64 == 0, K >= 128.
template <int NPROD>
__global__ __launch_bounds__(256, 1) void hmma_gemm(
    const __half* __restrict__ Ah, const __half* __restrict__ Al, size_t ldA,
    const __half* __restrict__ Bh, const __half* __restrict__ Bl, size_t ldB,
    int K, float alpha,
    float* __restrict__ Cf, __half* __restrict__ Ch, __half* __restrict__ Cl,
    int ldc)
{
    extern __shared__ char dynsm[];
    const uint32_t sbase = smem_u32(dynsm);

    const int tid  = threadIdx.x;
    const int wid  = tid >> 5;
    const int lane = tid & 31;
    const int mBase = blockIdx.y * 128;
    const int nBase = blockIdx.x * 128;
    const int nch = K >> 6;

    const int wm = wid & 3, wn = wid >> 2;

    // ---- load geometry: sel 0..3 -> Ah,Al,Bh,Bl; 2 rows/thread, 8 cp16/row
    const int sel  = tid >> 6;
    const int lrow = (tid & 63) * 2;
    const __half* gsrc;
    size_t gld;
    if (sel == 0)      { gsrc = Ah + (size_t)(mBase + lrow) * ldA; gld = ldA; }
    else if (sel == 1) { gsrc = Al + (size_t)(mBase + lrow) * ldA; gld = ldA; }
    else if (sel == 2) { gsrc = Bh + (size_t)(nBase + lrow) * ldB; gld = ldB; }
    else               { gsrc = Bl + (size_t)(nBase + lrow) * ldB; gld = ldB; }
    const uint32_t sdst0 = sbase + sel * MAT_BYTES + lrow * ROWB;
    const bool do_load = (NPROD == 3) || (sel != 1);

    #define LOAD_CHUNK(stg, k0) do {                                    \
        if (do_load) {                                                   \
            const uint32_t _d = sdst0 + (stg) * STG_BYTES;               \
            const __half* _s = gsrc + (k0);                              \
            _Pragma("unroll")                                            \
            for (int _j = 0; _j < 8; ++_j) {                             \
                cp16(_d + _j * 16,        _s + _j * 8);                  \
                cp16(_d + ROWB + _j * 16, _s + gld + _j * 8);            \
            }                                                            \
        }                                                                \
    } while (0)

    const int l15 = lane & 15;
    const int lc8 = (lane >> 4) << 3;

    float acc[2][8][4];
    #pragma unroll
    for (int i = 0; i < 2; ++i)
        #pragma unroll
        for (int j = 0; j < 8; ++j)
            #pragma unroll
            for (int q = 0; q < 4; ++q) acc[i][j][q] = 0.0f;

    // prologue: chunks 0,1 in flight
    LOAD_CHUNK(0, 0);
    CP_COMMIT();
    LOAD_CHUNK(1, 64);
    CP_COMMIT();

    for (int i = 0; i < nch; ++i) {
        CP_WAIT(1);
        __syncthreads();
        if (i + 2 < nch) { LOAD_CHUNK((i + 2) % NST, (i + 2) << 6); }
        CP_COMMIT();

        const uint32_t stg = sbase + (i % NST) * STG_BYTES;
        #pragma unroll
        for (int kk = 0; kk < 64; kk += 16) {
            uint32_t ah[2][4], al[2][4], bh[4][4], bl[4][4];
            #pragma unroll
            for (int mi = 0; mi < 2; ++mi) {
                const uint32_t ao = stg + (wm*32 + mi*16 + l15) * ROWB + (kk + lc8) * 2;
                LDSM4(ah[mi], ao);
                if (NPROD == 3) LDSM4(al[mi], ao + MAT_BYTES);
            }
            #pragma unroll
            for (int g = 0; g < 4; ++g) {
                const uint32_t bo = stg + 2*MAT_BYTES + (wn*64 + g*16 + l15) * ROWB + (kk + lc8) * 2;
                LDSM4(bh[g], bo);
                LDSM4(bl[g], bo + MAT_BYTES);
            }
            // product-major: dependent MMAs on same acc are 16 apart
            #pragma unroll
            for (int mi = 0; mi < 2; ++mi)
                #pragma unroll
                for (int g = 0; g < 4; ++g) {
                    MMA(acc[mi][2*g+0], ah[mi], bh[g][0], bh[g][2]);
                    MMA(acc[mi][2*g+1], ah[mi], bh[g][1], bh[g][3]);
                }
            #pragma unroll
            for (int mi = 0; mi < 2; ++mi)
                #pragma unroll
                for (int g = 0; g < 4; ++g) {
                    MMA(acc[mi][2*g+0], ah[mi], bl[g][0], bl[g][2]);
                    MMA(acc[mi][2*g+1], ah[mi], bl[g][1], bl[g][3]);
                }
            if (NPROD == 3) {
                #pragma unroll
                for (int mi = 0; mi < 2; ++mi)
                    #pragma unroll
                    for (int g = 0; g < 4; ++g) {
                        MMA(acc[mi][2*g+0], al[mi], bh[g][0], bh[g][2]);
                        MMA(acc[mi][2*g+1], al[mi], bh[g][1], bh[g][3]);
                    }
            }
        }
    }

    // ---- epilogue
    const int g4 = lane >> 2, t4 = lane & 3;
    #pragma unroll
    for (int mi = 0; mi < 2; ++mi) {
        #pragma unroll
        for (int nj = 0; nj < 8; ++nj) {
            const int r0 = mBase + wm*32 + mi*16 + g4;
            const int c0 = nBase + wn*64 + nj*8 + t4*2;
            float v0 = acc[mi][nj][0] * alpha, v1 = acc[mi][nj][1] * alpha;
            float v2 = acc[mi][nj][2] * alpha, v3 = acc[mi][nj][3] * alpha;
            if (Cf) {
                *reinterpret_cast<float2*>(Cf + (size_t)r0 * ldc + c0)       = make_float2(v0, v1);
                *reinterpret_cast<float2*>(Cf + (size_t)(r0+8) * ldc + c0)   = make_float2(v2, v3);
            } else {
                __half h0 = __float2half(v0), h1 = __float2half(v1);
                __half h2 = __float2half(v2), h3 = __float2half(v3);
                *reinterpret_cast<unsigned*>(Ch + (size_t)r0 * ldc + c0)     = pack2(h0, h1);
                *reinterpret_cast<unsigned*>(Ch + (size_t)(r0+8) * ldc + c0) = pack2(h2, h3);
                *reinterpret_cast<unsigned*>(Cl + (size_t)r0 * ldc + c0) =
                    pack2(__float2half(v0 - __half2float(h0)),
                          __float2half(v1 - __half2float(h1)));
                *reinterpret_cast<unsigned*>(Cl + (size_t)(r0+8) * ldc + c0) =
                    pack2(__float2half(v2 - __half2float(h2)),
                          __float2half(v3 - __half2float(h3)));
            }
        }
    }
}

// ---------------------------------------------------------------- small kernels
__global__ __launch_bounds__(256) void build_c_split(const float4* __restrict__ s,
                                                     const float4* __restrict__ tg,
                                                     const float4* __restrict__ q)
{
    const size_t i = (size_t)blockIdx.x * blockDim.x + threadIdx.x;
    float4 a = s[i], b = tg[i];
    float4 r; r.x = a.x + b.x; r.y = a.y + b.y; r.z = a.z + b.z; r.w = a.w + b.w;
    wr_hl4(g_ch, g_cl, i * 4, r);
    float4 qq = q[i];
    wr_hl4(g_ch, g_cl, (size_t)BSQ * CDIM + i * 4, qq);
}

__global__ __launch_bounds__(256) void cvt_w(const float4* __restrict__ w,
                                             __half* __restrict__ H,
                                             __half* __restrict__ L)
{
    const size_t i = (size_t)blockIdx.x * blockDim.x + threadIdx.x;
    wr_hl4(H, L, i * 4, w[i]);
}

// transpose fp32 [R x C] -> f16 hi/lo [C x R]
__global__ __launch_bounds__(256) void transpose_cvt(const float* __restrict__ in,
                                                     __half* __restrict__ oh,
                                                     __half* __restrict__ ol,
                                                     int R, int C)
{
    __shared__ float t[32][33];
    const int tx = threadIdx.x, ty = threadIdx.y;
    const int x = blockIdx.x * 32 + tx;
    #pragma unroll
    for (int j = 0; j < 4; ++j) {
        const int y = blockIdx.y * 32 + ty + j * 8;
        t[ty + j*8][tx] = in[(size_t)y * C + x];
    }
    __syncthreads();
    const int ox = blockIdx.y * 32 + tx;
    #pragma unroll
    for (int j = 0; j < 4; ++j) {
        const int oy = blockIdx.x * 32 + ty + j * 8;
        float v = t[tx][ty + j*8];
        __half h = __float2half(v);
        oh[(size_t)oy * R + ox] = h;
        ol[(size_t)oy * R + ox] = __float2half(v - __half2float(h));
    }
}

__global__ __launch_bounds__(512) void softmax_fused(const float* __restrict__ S)
{
    const float* p = S + (size_t)blockIdx.x * NTOT;
    const int t = threadIdx.x;
    float v[16];
    float m = -1e30f;
    #pragma unroll
    for (int i = 0; i < 16; ++i) { v[i] = p[t + i * 512]; m = fmaxf(m, v[i]); }

    __shared__ float red[16];
    #pragma unroll
    for (int o = 16; o; o >>= 1) m = fmaxf(m, __shfl_xor_sync(0xffffffffu, m, o));
    if ((t & 31) == 0) red[t >> 5] = m;
    __syncthreads();
    float mm = red[0];
    #pragma unroll
    for (int i = 1; i < 16; ++i) mm = fmaxf(mm, red[i]);

    float sum = 0.0f;
    #pragma unroll
    for (int i = 0; i < 16; ++i) { v[i] = __expf(v[i] - mm); sum += v[i]; }
    #pragma unroll
    for (int o = 16; o; o >>= 1) sum += __shfl_xor_sync(0xffffffffu, sum, o);
    __syncthreads();
    if ((t & 31) == 0) red[t >> 5] = sum;
    __syncthreads();
    float tot = 0.0f;
    #pragma unroll
    for (int i = 0; i < 16; ++i) tot += red[i];
    const float rcp = 1.0f / tot;

    if (blockIdx.x < BSQ) {
        const size_t rb = (size_t)blockIdx.x * BSQ;
        #pragma unroll
        for (int i = 8; i < 16; ++i) {
            const int col = t + (i - 8) * 512;
            float val = v[i] * rcp;
            __half h = __float2half(val);
            g_pcqh[rb + col] = h;
            g_pcql[rb + col] = __float2half(val - __half2float(h));
        }
    } else {
        const size_t rb = (size_t)(blockIdx.x - BSQ) * BSQ;
        #pragma unroll
        for (int i = 0; i < 8; ++i) {
            const int col = t + i * 512;
            float val = v[i] * rcp;
            __half h = __float2half(val);
            g_pqch[rb + col] = h;
            g_pqcl[rb + col] = __float2half(val - __half2float(h));
        }
    }
}

// ---------------------------------------------------------------- host
static void run_gemm(const __half* Ah, const __half* Al, size_t ldA,
                     const __half* Bh, const __half* Bl, size_t ldB,
                     int M, int N, int K, float alpha,
                     float* Cf, __half* Ch, __half* Cl, int ldc,
                     bool two_prod = false)
{
    if (two_prod)
        hmma_gemm<2><<<dim3(N / 128, M / 128), 256, SMEM_GEMM>>>(
            Ah, Al, ldA, Bh, Bl, ldB, K, alpha, Cf, Ch, Cl, ldc);
    else
        hmma_gemm<3><<<dim3(N / 128, M / 128), 256, SMEM_GEMM>>>(
            Ah, Al, ldA, Bh, Bl, ldB, K, alpha, Cf, Ch, Cl, ldc);
}

extern "C" void kernel_launch(void* const* d_in, const int* in_sizes, int n_in,
                              void* d_out, int out_size)
{
    const float* query = (const float*)d_in[0];
    const float* s     = (const float*)d_in[1];
    const float* tg    = (const float*)d_in[2];
    const float* Wqkv  = (const float*)d_in[3];
    const float* Wps   = (const float*)d_in[4];
    const float* Wpq   = (const float*)d_in[5];
    float* out = (float*)d_out;

    void* p;
    cudaGetSymbolAddress(&p, g_S);    float* S = (float*)p;
    cudaGetSymbolAddress(&p, g_ch);   __half* ch = (__half*)p;
    cudaGetSymbolAddress(&p, g_cl);   __half* cl = (__half*)p;
    cudaGetSymbolAddress(&p, g_wqTh); __half* wqTh = (__half*)p;
    cudaGetSymbolAddress(&p, g_wqTl); __half* wqTl = (__half*)p;
    cudaGetSymbolAddress(&p, g_wkTh); __half* wkTh = (__half*)p;
    cudaGetSymbolAddress(&p, g_wkTl); __half* wkTl = (__half*)p;
    cudaGetSymbolAddress(&p, g_mwth); __half* mwth = (__half*)p;
    cudaGetSymbolAddress(&p, g_mwtl); __half* mwtl = (__half*)p;
    cudaGetSymbolAddress(&p, g_zh);   __half* zh = (__half*)p;
    cudaGetSymbolAddress(&p, g_zl);   __half* zl = (__half*)p;
    cudaGetSymbolAddress(&p, g_wpsh); __half* wpsh = (__half*)p;
    cudaGetSymbolAddress(&p, g_wpsl); __half* wpsl = (__half*)p;
    cudaGetSymbolAddress(&p, g_wpqh); __half* wpqh = (__half*)p;
    cudaGetSymbolAddress(&p, g_wpql); __half* wpql = (__half*)p;
    cudaGetSymbolAddress(&p, g_pcqh); __half* pcqh = (__half*)p;
    cudaGetSymbolAddress(&p, g_pcql); __half* pcql = (__half*)p;
    cudaGetSymbolAddress(&p, g_pqch); __half* pqch = (__half*)p;
    cudaGetSymbolAddress(&p, g_pqcl); __half* pqcl = (__half*)p;
    cudaGetSymbolAddress(&p, g_qTh);  __half* qTh = (__half*)p;
    cudaGetSymbolAddress(&p, g_qTl);  __half* qTl = (__half*)p;
    cudaGetSymbolAddress(&p, g_sTh);  __half* sTh = (__half*)p;
    cudaGetSymbolAddress(&p, g_sTl);  __half* sTl = (__half*)p;
    cudaGetSymbolAddress(&p, g_t0h);  __half* t0h = (__half*)p;
    cudaGetSymbolAddress(&p, g_t0l);  __half* t0l = (__half*)p;
    cudaGetSymbolAddress(&p, g_t1h);  __half* t1h = (__half*)p;
    cudaGetSymbolAddress(&p, g_t1l);  __half* t1l = (__half*)p;

    cudaFuncSetAttribute(hmma_gemm<3>, cudaFuncAttributeMaxDynamicSharedMemorySize, SMEM_GEMM);
    cudaFuncSetAttribute(hmma_gemm<2>, cudaFuncAttributeMaxDynamicSharedMemorySize, SMEM_GEMM);

    // 1) c = [s+TG ; query] -> f16 hi/lo
    build_c_split<<<(BSQ * CDIM / 4) / 256, 256>>>(
        (const float4*)s, (const float4*)tg, (const float4*)query);

    // 2) projection weight conversions
    cvt_w<<<(HD * HD / 4) / 256, 256>>>((const float4*)Wps, wpsh, wpsl);
    cvt_w<<<(HD * HD / 4) / 256, 256>>>((const float4*)Wpq, wpqh, wpql);

    // 3) transposes: query^T, s^T (attn@V B operands), Wq^T, Wk^T
    transpose_cvt<<<dim3(CDIM / 32, BSQ / 32), dim3(32, 8)>>>(query, qTh, qTl, BSQ, CDIM);
    transpose_cvt<<<dim3(CDIM / 32, BSQ / 32), dim3(32, 8)>>>(s, sTh, sTl, BSQ, CDIM);
    transpose_cvt<<<dim3(CDIM / 32, HD / 32), dim3(32, 8)>>>(Wqkv, wqTh, wqTl, HD, CDIM);
    transpose_cvt<<<dim3(CDIM / 32, HD / 32), dim3(32, 8)>>>(Wqkv + (size_t)HD * CDIM,
                                                             wkTh, wkTl, HD, CDIM);

    // 4) MwT = SCALE^2 * Wk^T @ Wq  -> f16 hi/lo [1024 x 1024]
    run_gemm(wkTh, wkTl, HD, wqTh, wqTl, HD,
             CDIM, CDIM, HD, SCALE2_F, nullptr, mwth, mwtl, CDIM);

    // 5) Z = c @ MwT^T  -> f16 hi/lo [8192 x 1024]
    run_gemm(ch, cl, CDIM, mwth, mwtl, CDIM,
             NTOT, HD, CDIM, 1.0f, nullptr, zh, zl, HD);

    // 6) S = Z @ c^T (f32) [8192 x 8192] — 2-product (Z rounded to f16)
    run_gemm(zh, zl, HD, ch, cl, CDIM,
             NTOT, NTOT, HD, 1.0f, S, nullptr, nullptr, NTOT, /*two_prod=*/true);

    // 7) softmax + quadrant split -> f16 hi/lo
    softmax_fused<<<NTOT, 512>>>(S);

    // 8) t0 = Pcq @ query ; t1 = Pqc @ s  -> f16 hi/lo [4096 x 1024]
    run_gemm(pcqh, pcql, BSQ, qTh, qTl, BSQ,
             BSQ, HD, BSQ, 1.0f, nullptr, t0h, t0l, HD);
    run_gemm(pqch, pqcl, BSQ, sTh, sTl, BSQ,
             BSQ, HD, BSQ, 1.0f, nullptr, t1h, t1l, HD);

    // 9) x_s = t0 @ Wps^T ; x_q = t1 @ Wpq^T  (f32 into d_out)
    run_gemm(t0h, t0l, HD, wpsh, wpsl, HD,
             BSQ, HD, HD, 1.0f, out, nullptr, nullptr, HD);
    run_gemm(t1h, t1l, HD, wpqh, wpql, HD,
             BSQ, HD, HD, 1.0f, out + (size_t)BSQ * HD, nullptr, nullptr, HD);
}